// round 1
// baseline (speedup 1.0000x reference)
#include <cuda_runtime.h>
#include <math.h>

// Problem constants
#define M_TOK   65536          // B*nvars*H = 32*32*64 token rows
#define C_DIM   256
#define N_QKV   768
#define D_FF    512
#define NUNITS  8192           // B*nvars*NUM_HEADS = 32*32*8

// ---------------- scratch (device globals; no allocation in kernel_launch) ----------------
__device__ float g_qkv[(size_t)M_TOK * N_QKV];     // 192 MB
__device__ float g_ot [(size_t)M_TOK * C_DIM];     // 64 MB  out_tok, (b,n,head,h,d) order
__device__ float g_oh [(size_t)M_TOK * C_DIM];     // 64 MB  out_hid
__device__ float g_h  [2ull * M_TOK * D_FF];       // 256 MB FF hidden, both branches
__device__ float g_pre[(size_t)M_TOK * C_DIM];     // 64 MB  pre-final-BN
__device__ float g_psum[3 * 256 * 256];
__device__ float g_psq [3 * 256 * 256];
__device__ float g_S[3 * 256];                     // per-channel scale (g*rstd)
__device__ float g_T[3 * 256];                     // per-channel shift (b - mean*scale)

// ======================= GEMM 1: qkv = src @ w_qkv + b_qkv =======================
// M=65536, K=256, N=768. 128x128x8 tiles, 256 threads, 8x8 microtile.
__global__ void __launch_bounds__(256) k_gemm_qkv(
    const float* __restrict__ A, const float* __restrict__ W,
    const float* __restrict__ bias)
{
    constexpr int K = 256, N = N_QKV;
    __shared__ __align__(16) float As[8][128];
    __shared__ __align__(16) float Bs[8][128];
    const int tid  = threadIdx.x;
    const int cRow = blockIdx.y << 7;
    const int cCol = blockIdx.x << 7;
    const int aRow = tid >> 1,  aCol = (tid & 1) << 2;
    const int bRow = tid >> 5,  bCol = (tid & 31) << 2;
    const int ty   = (tid >> 4) << 3, tx = (tid & 15) << 3;

    const float* Ap = A + (size_t)(cRow + aRow) * K + aCol;
    const float* Wp = W + (size_t)bRow * N + cCol + bCol;

    float acc[8][8];
#pragma unroll
    for (int i = 0; i < 8; i++)
#pragma unroll
        for (int j = 0; j < 8; j++) acc[i][j] = 0.f;

    for (int k0 = 0; k0 < K; k0 += 8) {
        float4 a4 = *(const float4*)Ap;
        float4 b4 = *(const float4*)Wp;
        As[aCol + 0][aRow] = a4.x;
        As[aCol + 1][aRow] = a4.y;
        As[aCol + 2][aRow] = a4.z;
        As[aCol + 3][aRow] = a4.w;
        *(float4*)&Bs[bRow][bCol] = b4;
        __syncthreads();
#pragma unroll
        for (int kk = 0; kk < 8; kk++) {
            float4 a0 = *(const float4*)&As[kk][ty];
            float4 a1 = *(const float4*)&As[kk][ty + 4];
            float4 b0 = *(const float4*)&Bs[kk][tx];
            float4 b1 = *(const float4*)&Bs[kk][tx + 4];
            float ar[8] = {a0.x, a0.y, a0.z, a0.w, a1.x, a1.y, a1.z, a1.w};
            float br[8] = {b0.x, b0.y, b0.z, b0.w, b1.x, b1.y, b1.z, b1.w};
#pragma unroll
            for (int i = 0; i < 8; i++)
#pragma unroll
                for (int j = 0; j < 8; j++) acc[i][j] += ar[i] * br[j];
        }
        __syncthreads();
        Ap += 8;
        Wp += (size_t)8 * N;
    }
#pragma unroll
    for (int i = 0; i < 8; i++) {
        size_t row = (size_t)(cRow + ty + i);
#pragma unroll
        for (int j = 0; j < 8; j += 4) {
            int col = cCol + tx + j;
            float4 o;
            o.x = acc[i][j + 0] + bias[col + 0];
            o.y = acc[i][j + 1] + bias[col + 1];
            o.z = acc[i][j + 2] + bias[col + 2];
            o.w = acc[i][j + 3] + bias[col + 3];
            *(float4*)&g_qkv[row * N + col] = o;
        }
    }
}

// ======================= Attention: one block per (b,n,head) unit =======================
__global__ void __launch_bounds__(128) k_attn(
    const float* __restrict__ E,       // ema_matrix 64x64 (lower-triangular)
    const float* __restrict__ w_dpk, const float* __restrict__ b_dpk,
    const float* __restrict__ w_dpv, const float* __restrict__ b_dpv)
{
    __shared__ float sQ[64][33], sK[64][33], sV[64][33];
    __shared__ float sP[64][16];
    __shared__ float sKdp[16][32], sVdp[16][32];
    __shared__ float sEQ[64][33];
    __shared__ float sEK[16][32];
    __shared__ float sH[32][33];

    const int u    = blockIdx.x;
    const int head = u & 7;
    const int bn   = u >> 3;
    const int tid  = threadIdx.x;

    // ---- phase 1: load q,k,v (64x32 each) ----
    const float* base = g_qkv + (size_t)bn * (64 * N_QKV) + head * 32;
    for (int i = tid; i < 2048; i += 128) {
        int e = i >> 5, d = i & 31;
        const float* p = base + e * N_QKV + d;
        sQ[e][d] = p[0];
        sK[e][d] = p[256];
        sV[e][d] = p[512];
    }
    __syncthreads();

    // ---- phase 2: dyn-proj softmax for K ----
    if (tid < 64) {
        float l[16];
#pragma unroll
        for (int c = 0; c < 16; c++) l[c] = __ldg(&b_dpk[c]);
#pragma unroll 8
        for (int d = 0; d < 32; d++) {
            float kv = sK[tid][d];
#pragma unroll
            for (int c = 0; c < 16; c++) l[c] += kv * __ldg(&w_dpk[d * 16 + c]);
        }
        float m = l[0];
#pragma unroll
        for (int c = 1; c < 16; c++) m = fmaxf(m, l[c]);
        float s = 0.f;
#pragma unroll
        for (int c = 0; c < 16; c++) { l[c] = expf(l[c] - m); s += l[c]; }
        float inv = 1.f / s;
#pragma unroll
        for (int c = 0; c < 16; c++) sP[tid][c] = l[c] * inv;
    }
    __syncthreads();

    // ---- phase 3: k_dp (16x32) + ema(q) (64x32) ----
#pragma unroll
    for (int r = 0; r < 4; r++) {
        int i = tid + (r << 7);
        int c = i >> 5, d = i & 31;
        float acc = 0.f;
#pragma unroll 8
        for (int e = 0; e < 64; e++) acc += sP[e][c] * sK[e][d];
        sKdp[c][d] = acc;
    }
#pragma unroll
    for (int r = 0; r < 16; r++) {
        int i = tid + (r << 7);
        int g = i >> 5, d = i & 31;
        float acc = 0.f;
        for (int a = 0; a <= g; a++) acc += __ldg(&E[g * 64 + a]) * sQ[a][d];
        sEQ[g][d] = acc;
    }
    __syncthreads();

    // ---- phase 4: dyn-proj softmax for V ----
    if (tid < 64) {
        float l[16];
#pragma unroll
        for (int c = 0; c < 16; c++) l[c] = __ldg(&b_dpv[c]);
#pragma unroll 8
        for (int d = 0; d < 32; d++) {
            float vv = sV[tid][d];
#pragma unroll
            for (int c = 0; c < 16; c++) l[c] += vv * __ldg(&w_dpv[d * 16 + c]);
        }
        float m = l[0];
#pragma unroll
        for (int c = 1; c < 16; c++) m = fmaxf(m, l[c]);
        float s = 0.f;
#pragma unroll
        for (int c = 0; c < 16; c++) { l[c] = expf(l[c] - m); s += l[c]; }
        float inv = 1.f / s;
#pragma unroll
        for (int c = 0; c < 16; c++) sP[tid][c] = l[c] * inv;
    }
    __syncthreads();

    // ---- phase 5: v_dp (16x32) + ema(k_dp) (16x32) ----
#pragma unroll
    for (int r = 0; r < 4; r++) {
        int i = tid + (r << 7);
        int c = i >> 5, d = i & 31;
        float acc = 0.f;
#pragma unroll 8
        for (int e = 0; e < 64; e++) acc += sP[e][c] * sV[e][d];
        sVdp[c][d] = acc;
    }
#pragma unroll
    for (int r = 0; r < 4; r++) {
        int i = tid + (r << 7);
        int g = i >> 5, d = i & 31;      // g in [0,16)
        float acc = 0.f;
        for (int a = 0; a <= g; a++) acc += __ldg(&E[g * 64 + a]) * sKdp[a][d];
        sEK[g][d] = acc;
    }
    __syncthreads();

    // ---- phase 6: token attention (tid<64) || hidden attention scores (tid>=64) ----
    if (tid < 64) {
        const int e = tid;
        float st[16];
#pragma unroll
        for (int c = 0; c < 16; c++) {
            float acc = 0.f;
#pragma unroll
            for (int d = 0; d < 32; d++) acc += sEQ[e][d] * sEK[c][d];
            st[c] = acc * 5.656854249492381f;  // sqrt(hd)=sqrt(32)
        }
        float m = st[0];
#pragma unroll
        for (int c = 1; c < 16; c++) m = fmaxf(m, st[c]);
        float s = 0.f;
#pragma unroll
        for (int c = 0; c < 16; c++) { st[c] = expf(st[c] - m); s += st[c]; }
        float inv = 1.f / s;
#pragma unroll
        for (int c = 0; c < 16; c++) st[c] *= inv;
        // out_tok row -> overwrite own sEQ row (only this thread reads it)
#pragma unroll
        for (int d = 0; d < 32; d++) {
            float acc = 0.f;
#pragma unroll
            for (int c = 0; c < 16; c++) acc += st[c] * sVdp[c][d];
            sEQ[e][d] = acc;
        }
    } else {
        const int idx = tid - 64;
        const int e = idx >> 1, h = idx & 1;  // 2 threads per row, 16 cols each
        float sh[16];
#pragma unroll
        for (int j = 0; j < 16; j++) {
            const int f = (h << 4) + j;
            float acc = 0.f;
#pragma unroll 8
            for (int a = 0; a < 64; a++) acc += sQ[a][e] * sK[a][f];
            sh[j] = acc * 8.0f;               // sqrt(H)=8
        }
        float m = sh[0];
#pragma unroll
        for (int j = 1; j < 16; j++) m = fmaxf(m, sh[j]);
        m = fmaxf(m, __shfl_xor_sync(0xffffffffu, m, 1));
        float s = 0.f;
#pragma unroll
        for (int j = 0; j < 16; j++) { sh[j] = expf(sh[j] - m); s += sh[j]; }
        s += __shfl_xor_sync(0xffffffffu, s, 1);
        float inv = 1.f / s;
#pragma unroll
        for (int j = 0; j < 16; j++) sH[e][(h << 4) + j] = sh[j] * inv;
    }
    __syncthreads();

    // ---- phase 7: coalesced out_tok store + out_hid compute/store ----
    float* otp = g_ot + (size_t)u * 2048;
    float* ohp = g_oh + (size_t)u * 2048;
#pragma unroll
    for (int r = 0; r < 16; r++) {
        int i = tid + (r << 7);
        int a = i >> 5, e = i & 31;
        otp[i] = sEQ[a][e];
        float acc = 0.f;
#pragma unroll
        for (int f = 0; f < 32; f++) acc += sH[e][f] * sV[a][f];
        ohp[i] = acc;
    }
}

// ======================= BN statistics (deterministic two-stage) =======================
__global__ void __launch_bounds__(256) k_bn_partial(int slot)
{
    const float* x = (slot == 0) ? g_ot : (slot == 1) ? g_oh : g_pre;
    const int c = threadIdx.x;              // channel = flat index % 256
    const size_t base = (size_t)blockIdx.x * 65536;  // 256 rows of 256
    float s = 0.f, q = 0.f;
    for (int r = 0; r < 256; r++) {
        float v = x[base + (size_t)(r << 8) + c];
        s += v;
        q += v * v;
    }
    g_psum[slot * 65536 + (blockIdx.x << 8) + c] = s;
    g_psq [slot * 65536 + (blockIdx.x << 8) + c] = q;
}

__global__ void __launch_bounds__(256) k_bn_finalize(
    int slot, const float* __restrict__ g, const float* __restrict__ b)
{
    const int c = threadIdx.x;
    const float* ps = g_psum + slot * 65536;
    const float* pq = g_psq  + slot * 65536;
    float s = 0.f, q = 0.f;
    for (int i = 0; i < 256; i++) { s += ps[(i << 8) + c]; q += pq[(i << 8) + c]; }
    const float inv = 1.f / 65536.f;
    float mean = s * inv;
    float var  = q * inv - mean * mean;
    float rstd = rsqrtf(var + 1e-5f);
    float sc = g[c] * rstd;
    g_S[slot * 256 + c] = sc;
    g_T[slot * 256 + c] = b[c] - mean * sc;
}

// ======================= GEMM 2: h = gelu(BN(o) @ W1 + b1), both branches =======================
__global__ void __launch_bounds__(256) k_ff1(
    const float* __restrict__ W1a, const float* __restrict__ W1b,
    const float* __restrict__ b1a, const float* __restrict__ b1b)
{
    constexpr int K = 256, N = D_FF;
    const int bz = blockIdx.z;
    const float* A    = bz ? g_oh : g_ot;
    const float* W    = bz ? W1b : W1a;
    const float* bias = bz ? b1b : b1a;
    const float* Sc = g_S + bz * 256;
    const float* Tc = g_T + bz * 256;
    float* C = g_h + (size_t)bz * ((size_t)M_TOK * D_FF);

    __shared__ __align__(16) float As[8][128];
    __shared__ __align__(16) float Bs[8][128];
    const int tid  = threadIdx.x;
    const int cRow = blockIdx.y << 7;
    const int cCol = blockIdx.x << 7;
    const int aRow = tid >> 1,  aCol = (tid & 1) << 2;
    const int bRow = tid >> 5,  bCol = (tid & 31) << 2;
    const int ty   = (tid >> 4) << 3, tx = (tid & 15) << 3;

    const float* Ap = A + (size_t)(cRow + aRow) * K + aCol;
    const float* Wp = W + (size_t)bRow * N + cCol + bCol;

    float acc[8][8];
#pragma unroll
    for (int i = 0; i < 8; i++)
#pragma unroll
        for (int j = 0; j < 8; j++) acc[i][j] = 0.f;

    for (int k0 = 0; k0 < K; k0 += 8) {
        const int kc = k0 + aCol;
        float4 a4 = *(const float4*)Ap;
        a4.x = a4.x * Sc[kc + 0] + Tc[kc + 0];      // BN applied on load (per K-column)
        a4.y = a4.y * Sc[kc + 1] + Tc[kc + 1];
        a4.z = a4.z * Sc[kc + 2] + Tc[kc + 2];
        a4.w = a4.w * Sc[kc + 3] + Tc[kc + 3];
        float4 b4 = *(const float4*)Wp;
        As[aCol + 0][aRow] = a4.x;
        As[aCol + 1][aRow] = a4.y;
        As[aCol + 2][aRow] = a4.z;
        As[aCol + 3][aRow] = a4.w;
        *(float4*)&Bs[bRow][bCol] = b4;
        __syncthreads();
#pragma unroll
        for (int kk = 0; kk < 8; kk++) {
            float4 a0 = *(const float4*)&As[kk][ty];
            float4 a1 = *(const float4*)&As[kk][ty + 4];
            float4 b0 = *(const float4*)&Bs[kk][tx];
            float4 b1 = *(const float4*)&Bs[kk][tx + 4];
            float ar[8] = {a0.x, a0.y, a0.z, a0.w, a1.x, a1.y, a1.z, a1.w};
            float br[8] = {b0.x, b0.y, b0.z, b0.w, b1.x, b1.y, b1.z, b1.w};
#pragma unroll
            for (int i = 0; i < 8; i++)
#pragma unroll
                for (int j = 0; j < 8; j++) acc[i][j] += ar[i] * br[j];
        }
        __syncthreads();
        Ap += 8;
        Wp += (size_t)8 * N;
    }
#pragma unroll
    for (int i = 0; i < 8; i++) {
        size_t row = (size_t)(cRow + ty + i);
#pragma unroll
        for (int j = 0; j < 8; j += 4) {
            int col = cCol + tx + j;
            float4 o;
            float v0 = acc[i][j + 0] + bias[col + 0];
            float v1 = acc[i][j + 1] + bias[col + 1];
            float v2 = acc[i][j + 2] + bias[col + 2];
            float v3 = acc[i][j + 3] + bias[col + 3];
            // exact GELU (approximate=False)
            o.x = 0.5f * v0 * (1.f + erff(v0 * 0.70710678118654752f));
            o.y = 0.5f * v1 * (1.f + erff(v1 * 0.70710678118654752f));
            o.z = 0.5f * v2 * (1.f + erff(v2 * 0.70710678118654752f));
            o.w = 0.5f * v3 * (1.f + erff(v3 * 0.70710678118654752f));
            *(float4*)&C[row * N + col] = o;
        }
    }
}

// ======================= GEMM 3: pre = src + h1@W2a + h2@W2b + b2a + b2b =======================
__global__ void __launch_bounds__(256) k_gemm2(
    const float* __restrict__ W2a, const float* __restrict__ W2b,
    const float* __restrict__ b2a, const float* __restrict__ b2b,
    const float* __restrict__ src)
{
    constexpr int K = D_FF, N = C_DIM;
    __shared__ __align__(16) float As[8][128];
    __shared__ __align__(16) float Bs[8][128];
    const int tid  = threadIdx.x;
    const int cRow = blockIdx.y << 7;
    const int cCol = blockIdx.x << 7;
    const int aRow = tid >> 1,  aCol = (tid & 1) << 2;
    const int bRow = tid >> 5,  bCol = (tid & 31) << 2;
    const int ty   = (tid >> 4) << 3, tx = (tid & 15) << 3;

    float acc[8][8];
#pragma unroll
    for (int i = 0; i < 8; i++)
#pragma unroll
        for (int j = 0; j < 8; j++) acc[i][j] = 0.f;

    for (int p = 0; p < 2; p++) {
        const float* Ap = g_h + (size_t)p * ((size_t)M_TOK * D_FF)
                          + (size_t)(cRow + aRow) * K + aCol;
        const float* Wp = (p ? W2b : W2a) + (size_t)bRow * N + cCol + bCol;
        for (int k0 = 0; k0 < K; k0 += 8) {
            float4 a4 = *(const float4*)Ap;
            float4 b4 = *(const float4*)Wp;
            As[aCol + 0][aRow] = a4.x;
            As[aCol + 1][aRow] = a4.y;
            As[aCol + 2][aRow] = a4.z;
            As[aCol + 3][aRow] = a4.w;
            *(float4*)&Bs[bRow][bCol] = b4;
            __syncthreads();
#pragma unroll
            for (int kk = 0; kk < 8; kk++) {
                float4 a0 = *(const float4*)&As[kk][ty];
                float4 a1 = *(const float4*)&As[kk][ty + 4];
                float4 b0 = *(const float4*)&Bs[kk][tx];
                float4 b1 = *(const float4*)&Bs[kk][tx + 4];
                float ar[8] = {a0.x, a0.y, a0.z, a0.w, a1.x, a1.y, a1.z, a1.w};
                float br[8] = {b0.x, b0.y, b0.z, b0.w, b1.x, b1.y, b1.z, b1.w};
#pragma unroll
                for (int i = 0; i < 8; i++)
#pragma unroll
                    for (int j = 0; j < 8; j++) acc[i][j] += ar[i] * br[j];
            }
            __syncthreads();
            Ap += 8;
            Wp += (size_t)8 * N;
        }
    }
#pragma unroll
    for (int i = 0; i < 8; i++) {
        size_t row = (size_t)(cRow + ty + i);
#pragma unroll
        for (int j = 0; j < 8; j += 4) {
            int col = cCol + tx + j;
            float4 sv = *(const float4*)&src[row * N + col];
            float4 o;
            o.x = acc[i][j + 0] + b2a[col + 0] + b2b[col + 0] + sv.x;
            o.y = acc[i][j + 1] + b2a[col + 1] + b2b[col + 1] + sv.y;
            o.z = acc[i][j + 2] + b2a[col + 2] + b2b[col + 2] + sv.z;
            o.w = acc[i][j + 3] + b2a[col + 3] + b2b[col + 3] + sv.w;
            *(float4*)&g_pre[row * N + col] = o;
        }
    }
}

// ======================= Final BN apply =======================
__global__ void __launch_bounds__(256) k_bn_apply(float* __restrict__ out)
{
    const size_t i = (size_t)blockIdx.x * 256 + threadIdx.x;  // float4 index
    float4 v = ((const float4*)g_pre)[i];
    const int c = (int)((i & 63) << 2);
    const float* S = g_S + 512;
    const float* T = g_T + 512;
    v.x = v.x * S[c + 0] + T[c + 0];
    v.y = v.y * S[c + 1] + T[c + 1];
    v.z = v.z * S[c + 2] + T[c + 2];
    v.w = v.w * S[c + 3] + T[c + 3];
    ((float4*)out)[i] = v;
}

// ======================= launch =======================
extern "C" void kernel_launch(void* const* d_in, const int* in_sizes, int n_in,
                              void* d_out, int out_size)
{
    const float* src    = (const float*)d_in[0];
    const float* ema    = (const float*)d_in[1];
    const float* w_qkv  = (const float*)d_in[2];
    const float* b_qkv  = (const float*)d_in[3];
    const float* w_dpk  = (const float*)d_in[4];
    const float* b_dpk  = (const float*)d_in[5];
    const float* w_dpv  = (const float*)d_in[6];
    const float* b_dpv  = (const float*)d_in[7];
    const float* bn1_g  = (const float*)d_in[8];
    const float* bn1_b  = (const float*)d_in[9];
    const float* bn2_g  = (const float*)d_in[10];
    const float* bn2_b  = (const float*)d_in[11];
    const float* bna_g  = (const float*)d_in[12];
    const float* bna_b  = (const float*)d_in[13];
    const float* ff1_w1 = (const float*)d_in[14];
    const float* ff1_b1 = (const float*)d_in[15];
    const float* ff1_w2 = (const float*)d_in[16];
    const float* ff1_b2 = (const float*)d_in[17];
    const float* ff2_w1 = (const float*)d_in[18];
    const float* ff2_b1 = (const float*)d_in[19];
    const float* ff2_w2 = (const float*)d_in[20];
    const float* ff2_b2 = (const float*)d_in[21];
    float* out = (float*)d_out;

    k_gemm_qkv<<<dim3(N_QKV / 128, M_TOK / 128), 256>>>(src, w_qkv, b_qkv);
    k_attn<<<NUNITS, 128>>>(ema, w_dpk, b_dpk, w_dpv, b_dpv);
    k_bn_partial<<<256, 256>>>(0);
    k_bn_partial<<<256, 256>>>(1);
    k_bn_finalize<<<1, 256>>>(0, bn1_g, bn1_b);
    k_bn_finalize<<<1, 256>>>(1, bn2_g, bn2_b);
    k_ff1<<<dim3(D_FF / 128, M_TOK / 128, 2), 256>>>(ff1_w1, ff2_w1, ff1_b1, ff2_b1);
    k_gemm2<<<dim3(C_DIM / 128, M_TOK / 128), 256>>>(ff1_w2, ff2_w2, ff1_b2, ff2_b2, src);
    k_bn_partial<<<256, 256>>>(2);
    k_bn_finalize<<<1, 256>>>(2, bna_g, bna_b);
    k_bn_apply<<<(M_TOK * C_DIM / 4) / 256, 256>>>(out);
}

// round 4
// speedup vs baseline: 1.2004x; 1.2004x over previous
#include <cuda_runtime.h>
#include <math.h>
#include <stdint.h>

// Problem constants
#define M_TOK   65536          // B*nvars*H = 32*32*64 token rows
#define C_DIM   256
#define N_QKV   768
#define D_FF    512
#define NUNITS  8192           // B*nvars*NUM_HEADS

// ---------------- scratch ----------------
__device__ float g_qkv[(size_t)M_TOK * N_QKV];
__device__ float g_ot [(size_t)M_TOK * C_DIM];
__device__ float g_oh [(size_t)M_TOK * C_DIM];
__device__ float g_h  [2ull * M_TOK * D_FF];
__device__ float g_pre[(size_t)M_TOK * C_DIM];
__device__ float g_psum[3 * 256 * 256];
__device__ float g_psq [3 * 256 * 256];
__device__ float g_S[3 * 256];
__device__ float g_T[3 * 256];

// ---------------- tf32 helpers ----------------
__device__ __forceinline__ uint32_t f2tf(float f) {
    uint32_t u;
    asm("cvt.rna.tf32.f32 %0, %1;" : "=r"(u) : "f"(f));
    return u;
}
__device__ __forceinline__ void mma8(float* d, const uint32_t* a, const uint32_t* b) {
    asm volatile(
        "mma.sync.aligned.m16n8k8.row.col.f32.tf32.tf32.f32 "
        "{%0,%1,%2,%3},{%4,%5,%6,%7},{%8,%9},{%0,%1,%2,%3};"
        : "+f"(d[0]), "+f"(d[1]), "+f"(d[2]), "+f"(d[3])
        : "r"(a[0]), "r"(a[1]), "r"(a[2]), "r"(a[3]), "r"(b[0]), "r"(b[1]));
}

// K-chunk = 16. Hi/Lo split operands (3xTF32): fp32-accurate tensor-core GEMM.
//  A stride 20: (gid*20 + tig)%32 spans all 32 banks
//  B stride 136: (tig*136 + gid)%32 = 8*tig+gid spans all 32 banks
#define AS_STRIDE 20
#define BS_STRIDE 136

// ---- shared per-kernel boilerplate ----
#define GEMM_PROLOG() \
    const int tid = threadIdx.x, lane = tid & 31, w = tid >> 5; \
    const int gid = lane >> 2, tig = lane & 3; \
    const int m_off = (w >> 2) * 64, n_off = (w & 3) * 32; \
    const int cRow = blockIdx.y << 7, cCol = blockIdx.x << 7; \
    const int a_r = tid >> 2, a_c4 = (tid & 3) << 2; \
    const int b_r = tid >> 4, b_c8 = (tid & 15) << 3; \
    float pa[8], pb[8]; \
    float acc[4][4][4]; \
    _Pragma("unroll") for (int i = 0; i < 4; i++) \
    _Pragma("unroll") for (int j = 0; j < 4; j++) \
    _Pragma("unroll") for (int r = 0; r < 4; r++) acc[i][j][r] = 0.f;

#define STORE_HILO() { \
    _Pragma("unroll") for (int r_ = 0; r_ < 2; r_++) { \
        uint4 uh_, ul_; \
        uh_.x = f2tf(pa[r_*4+0]); ul_.x = f2tf(pa[r_*4+0] - __uint_as_float(uh_.x)); \
        uh_.y = f2tf(pa[r_*4+1]); ul_.y = f2tf(pa[r_*4+1] - __uint_as_float(uh_.y)); \
        uh_.z = f2tf(pa[r_*4+2]); ul_.z = f2tf(pa[r_*4+2] - __uint_as_float(uh_.z)); \
        uh_.w = f2tf(pa[r_*4+3]); ul_.w = f2tf(pa[r_*4+3] - __uint_as_float(uh_.w)); \
        int row_ = a_r + r_ * 64; \
        *(uint4*)&AsH[row_ * AS_STRIDE + a_c4] = uh_; \
        *(uint4*)&AsL[row_ * AS_STRIDE + a_c4] = ul_; } \
    _Pragma("unroll") for (int q_ = 0; q_ < 2; q_++) { \
        uint4 uh_, ul_; \
        uh_.x = f2tf(pb[q_*4+0]); ul_.x = f2tf(pb[q_*4+0] - __uint_as_float(uh_.x)); \
        uh_.y = f2tf(pb[q_*4+1]); ul_.y = f2tf(pb[q_*4+1] - __uint_as_float(uh_.y)); \
        uh_.z = f2tf(pb[q_*4+2]); ul_.z = f2tf(pb[q_*4+2] - __uint_as_float(uh_.z)); \
        uh_.w = f2tf(pb[q_*4+3]); ul_.w = f2tf(pb[q_*4+3] - __uint_as_float(uh_.w)); \
        *(uint4*)&BsH[b_r * BS_STRIDE + b_c8 + q_ * 4] = uh_; \
        *(uint4*)&BsL[b_r * BS_STRIDE + b_c8 + q_ * 4] = ul_; } }

#define COMPUTE_CHUNK() { \
    _Pragma("unroll") for (int kk = 0; kk < 2; kk++) { \
        uint32_t afH[4][4], afL[4][4], bfH[4][2], bfL[4][2]; \
        _Pragma("unroll") for (int i = 0; i < 4; i++) { \
            int r0 = (m_off + i * 16 + gid) * AS_STRIDE + kk * 8 + tig; \
            int r1 = r0 + 8 * AS_STRIDE; \
            afH[i][0] = AsH[r0];     afH[i][1] = AsH[r1]; \
            afH[i][2] = AsH[r0 + 4]; afH[i][3] = AsH[r1 + 4]; \
            afL[i][0] = AsL[r0];     afL[i][1] = AsL[r1]; \
            afL[i][2] = AsL[r0 + 4]; afL[i][3] = AsL[r1 + 4]; } \
        _Pragma("unroll") for (int j = 0; j < 4; j++) { \
            int c0 = (kk * 8 + tig) * BS_STRIDE + n_off + j * 8 + gid; \
            bfH[j][0] = BsH[c0]; bfH[j][1] = BsH[c0 + 4 * BS_STRIDE]; \
            bfL[j][0] = BsL[c0]; bfL[j][1] = BsL[c0 + 4 * BS_STRIDE]; } \
        _Pragma("unroll") for (int i = 0; i < 4; i++) \
        _Pragma("unroll") for (int j = 0; j < 4; j++) { \
            mma8(acc[i][j], afL[i], bfH[j]); \
            mma8(acc[i][j], afH[i], bfL[j]); \
            mma8(acc[i][j], afH[i], bfH[j]); } } }

// ======================= GEMM 1: qkv = src @ w_qkv + b_qkv =======================
__global__ void __launch_bounds__(256, 1) k_gemm_qkv_tc(
    const float* __restrict__ A, const float* __restrict__ W,
    const float* __restrict__ bias)
{
    constexpr int K = 256, N = N_QKV, NIT = K / 16;
    __shared__ uint32_t AsH[128 * AS_STRIDE], AsL[128 * AS_STRIDE];
    __shared__ uint32_t BsH[16 * BS_STRIDE],  BsL[16 * BS_STRIDE];
    GEMM_PROLOG();

#define QKV_LOADA(it) { \
    const float* p_ = A + (size_t)(cRow + a_r) * K + (it) * 16 + a_c4; \
    float4 v_ = *(const float4*)p_; \
    pa[0]=v_.x; pa[1]=v_.y; pa[2]=v_.z; pa[3]=v_.w; \
    v_ = *(const float4*)(p_ + (size_t)64 * K); \
    pa[4]=v_.x; pa[5]=v_.y; pa[6]=v_.z; pa[7]=v_.w; }
#define QKV_LOADB(it) { \
    const float* p_ = W + (size_t)((it) * 16 + b_r) * N + cCol + b_c8; \
    float4 v_ = *(const float4*)p_; \
    pb[0]=v_.x; pb[1]=v_.y; pb[2]=v_.z; pb[3]=v_.w; \
    v_ = *(const float4*)(p_ + 4); \
    pb[4]=v_.x; pb[5]=v_.y; pb[6]=v_.z; pb[7]=v_.w; }

    QKV_LOADA(0); QKV_LOADB(0); STORE_HILO();
    __syncthreads();
    for (int it = 0; it < NIT; it++) {
        if (it + 1 < NIT) { QKV_LOADA(it + 1); QKV_LOADB(it + 1); }
        COMPUTE_CHUNK();
        __syncthreads();
        if (it + 1 < NIT) { STORE_HILO(); __syncthreads(); }
    }

#pragma unroll
    for (int i = 0; i < 4; i++)
#pragma unroll
        for (int j = 0; j < 4; j++) {
            int row0 = cRow + m_off + i * 16 + gid;
            int col  = cCol + n_off + j * 8 + tig * 2;
            float b0 = bias[col], b1 = bias[col + 1];
            float2 v0 = {acc[i][j][0] + b0, acc[i][j][1] + b1};
            float2 v1 = {acc[i][j][2] + b0, acc[i][j][3] + b1};
            *(float2*)&g_qkv[(size_t)row0 * N + col] = v0;
            *(float2*)&g_qkv[(size_t)(row0 + 8) * N + col] = v1;
        }
}

// ======================= GEMM 2: h = gelu(BN(o) @ W1 + b1) =======================
__global__ void __launch_bounds__(256, 1) k_ff1_tc(
    const float* __restrict__ W1a, const float* __restrict__ W1b,
    const float* __restrict__ b1a, const float* __restrict__ b1b)
{
    constexpr int K = 256, N = D_FF, NIT = K / 16;
    __shared__ uint32_t AsH[128 * AS_STRIDE], AsL[128 * AS_STRIDE];
    __shared__ uint32_t BsH[16 * BS_STRIDE],  BsL[16 * BS_STRIDE];
    __shared__ float sS[256], sT[256];

    const int bz = blockIdx.z;
    const float* A    = bz ? g_oh : g_ot;
    const float* W    = bz ? W1b : W1a;
    const float* bias = bz ? b1b : b1a;
    float* Cout = g_h + (size_t)bz * ((size_t)M_TOK * D_FF);

    GEMM_PROLOG();
    sS[tid] = g_S[bz * 256 + tid];
    sT[tid] = g_T[bz * 256 + tid];
    __syncthreads();

#define FF1_LOADA(it) { \
    const int kb_ = (it) * 16 + a_c4; \
    const float* p_ = A + (size_t)(cRow + a_r) * K + kb_; \
    float4 v_ = *(const float4*)p_; \
    pa[0]=v_.x*sS[kb_+0]+sT[kb_+0]; pa[1]=v_.y*sS[kb_+1]+sT[kb_+1]; \
    pa[2]=v_.z*sS[kb_+2]+sT[kb_+2]; pa[3]=v_.w*sS[kb_+3]+sT[kb_+3]; \
    v_ = *(const float4*)(p_ + (size_t)64 * K); \
    pa[4]=v_.x*sS[kb_+0]+sT[kb_+0]; pa[5]=v_.y*sS[kb_+1]+sT[kb_+1]; \
    pa[6]=v_.z*sS[kb_+2]+sT[kb_+2]; pa[7]=v_.w*sS[kb_+3]+sT[kb_+3]; }
#define FF1_LOADB(it) { \
    const float* p_ = W + (size_t)((it) * 16 + b_r) * N + cCol + b_c8; \
    float4 v_ = *(const float4*)p_; \
    pb[0]=v_.x; pb[1]=v_.y; pb[2]=v_.z; pb[3]=v_.w; \
    v_ = *(const float4*)(p_ + 4); \
    pb[4]=v_.x; pb[5]=v_.y; pb[6]=v_.z; pb[7]=v_.w; }

    FF1_LOADA(0); FF1_LOADB(0); STORE_HILO();
    __syncthreads();
    for (int it = 0; it < NIT; it++) {
        if (it + 1 < NIT) { FF1_LOADA(it + 1); FF1_LOADB(it + 1); }
        COMPUTE_CHUNK();
        __syncthreads();
        if (it + 1 < NIT) { STORE_HILO(); __syncthreads(); }
    }

#pragma unroll
    for (int i = 0; i < 4; i++)
#pragma unroll
        for (int j = 0; j < 4; j++) {
            int row0 = cRow + m_off + i * 16 + gid;
            int col  = cCol + n_off + j * 8 + tig * 2;
            float b0 = bias[col], b1 = bias[col + 1];
            float x0 = acc[i][j][0] + b0, x1 = acc[i][j][1] + b1;
            float x2 = acc[i][j][2] + b0, x3 = acc[i][j][3] + b1;
            float2 v0, v1;
            v0.x = 0.5f * x0 * (1.f + erff(x0 * 0.70710678118654752f));
            v0.y = 0.5f * x1 * (1.f + erff(x1 * 0.70710678118654752f));
            v1.x = 0.5f * x2 * (1.f + erff(x2 * 0.70710678118654752f));
            v1.y = 0.5f * x3 * (1.f + erff(x3 * 0.70710678118654752f));
            *(float2*)&Cout[(size_t)row0 * N + col] = v0;
            *(float2*)&Cout[(size_t)(row0 + 8) * N + col] = v1;
        }
}

// ======================= GEMM 3: pre = src + h1@W2a + h2@W2b + biases =======================
__global__ void __launch_bounds__(256, 1) k_gemm2_tc(
    const float* __restrict__ W2a, const float* __restrict__ W2b,
    const float* __restrict__ b2a, const float* __restrict__ b2b,
    const float* __restrict__ src)
{
    constexpr int K = D_FF, N = C_DIM, NIT = 2 * K / 16;  // 64 iters across 2 branches
    __shared__ uint32_t AsH[128 * AS_STRIDE], AsL[128 * AS_STRIDE];
    __shared__ uint32_t BsH[16 * BS_STRIDE],  BsL[16 * BS_STRIDE];
    GEMM_PROLOG();

#define G2_LOADAB(it) { \
    const int p_ = (it) >> 5, k0_ = ((it) & 31) * 16; \
    const float* Ap_ = g_h + (size_t)p_ * ((size_t)M_TOK * D_FF) \
                       + (size_t)(cRow + a_r) * K + k0_ + a_c4; \
    float4 v_ = *(const float4*)Ap_; \
    pa[0]=v_.x; pa[1]=v_.y; pa[2]=v_.z; pa[3]=v_.w; \
    v_ = *(const float4*)(Ap_ + (size_t)64 * K); \
    pa[4]=v_.x; pa[5]=v_.y; pa[6]=v_.z; pa[7]=v_.w; \
    const float* Wp_ = (p_ ? W2b : W2a) + (size_t)(k0_ + b_r) * N + cCol + b_c8; \
    v_ = *(const float4*)Wp_; \
    pb[0]=v_.x; pb[1]=v_.y; pb[2]=v_.z; pb[3]=v_.w; \
    v_ = *(const float4*)(Wp_ + 4); \
    pb[4]=v_.x; pb[5]=v_.y; pb[6]=v_.z; pb[7]=v_.w; }

    G2_LOADAB(0); STORE_HILO();
    __syncthreads();
    for (int it = 0; it < NIT; it++) {
        if (it + 1 < NIT) { G2_LOADAB(it + 1); }
        COMPUTE_CHUNK();
        __syncthreads();
        if (it + 1 < NIT) { STORE_HILO(); __syncthreads(); }
    }

#pragma unroll
    for (int i = 0; i < 4; i++)
#pragma unroll
        for (int j = 0; j < 4; j++) {
            int row0 = cRow + m_off + i * 16 + gid;
            int col  = cCol + n_off + j * 8 + tig * 2;
            float b0 = b2a[col] + b2b[col], b1 = b2a[col + 1] + b2b[col + 1];
            float2 s0 = *(const float2*)&src[(size_t)row0 * N + col];
            float2 s1 = *(const float2*)&src[(size_t)(row0 + 8) * N + col];
            float2 v0 = {acc[i][j][0] + b0 + s0.x, acc[i][j][1] + b1 + s0.y};
            float2 v1 = {acc[i][j][2] + b0 + s1.x, acc[i][j][3] + b1 + s1.y};
            *(float2*)&g_pre[(size_t)row0 * N + col] = v0;
            *(float2*)&g_pre[(size_t)(row0 + 8) * N + col] = v1;
        }
}

// ======================= Attention: one block per (b,n,head) unit =======================
__global__ void __launch_bounds__(128) k_attn(
    const float* __restrict__ E,
    const float* __restrict__ w_dpk, const float* __restrict__ b_dpk,
    const float* __restrict__ w_dpv, const float* __restrict__ b_dpv)
{
    __shared__ float sQ[64][33], sK[64][33], sV[64][33];
    __shared__ float sP[64][16];
    __shared__ float sKdp[16][32], sVdp[16][32];
    __shared__ float sEQ[64][33];
    __shared__ float sEK[16][32];
    __shared__ float sH[32][33];

    const int u    = blockIdx.x;
    const int head = u & 7;
    const int bn   = u >> 3;
    const int tid  = threadIdx.x;

    const float* base = g_qkv + (size_t)bn * (64 * N_QKV) + head * 32;
    for (int i = tid; i < 2048; i += 128) {
        int e = i >> 5, d = i & 31;
        const float* p = base + e * N_QKV + d;
        sQ[e][d] = p[0];
        sK[e][d] = p[256];
        sV[e][d] = p[512];
    }
    __syncthreads();

    if (tid < 64) {
        float l[16];
#pragma unroll
        for (int c = 0; c < 16; c++) l[c] = __ldg(&b_dpk[c]);
#pragma unroll 8
        for (int d = 0; d < 32; d++) {
            float kv = sK[tid][d];
#pragma unroll
            for (int c = 0; c < 16; c++) l[c] += kv * __ldg(&w_dpk[d * 16 + c]);
        }
        float m = l[0];
#pragma unroll
        for (int c = 1; c < 16; c++) m = fmaxf(m, l[c]);
        float s = 0.f;
#pragma unroll
        for (int c = 0; c < 16; c++) { l[c] = expf(l[c] - m); s += l[c]; }
        float inv = 1.f / s;
#pragma unroll
        for (int c = 0; c < 16; c++) sP[tid][c] = l[c] * inv;
    }
    __syncthreads();

#pragma unroll
    for (int r = 0; r < 4; r++) {
        int i = tid + (r << 7);
        int c = i >> 5, d = i & 31;
        float acc = 0.f;
#pragma unroll 8
        for (int e = 0; e < 64; e++) acc += sP[e][c] * sK[e][d];
        sKdp[c][d] = acc;
    }
#pragma unroll
    for (int r = 0; r < 16; r++) {
        int i = tid + (r << 7);
        int g = i >> 5, d = i & 31;
        float acc = 0.f;
        for (int a = 0; a <= g; a++) acc += __ldg(&E[g * 64 + a]) * sQ[a][d];
        sEQ[g][d] = acc;
    }
    __syncthreads();

    if (tid < 64) {
        float l[16];
#pragma unroll
        for (int c = 0; c < 16; c++) l[c] = __ldg(&b_dpv[c]);
#pragma unroll 8
        for (int d = 0; d < 32; d++) {
            float vv = sV[tid][d];
#pragma unroll
            for (int c = 0; c < 16; c++) l[c] += vv * __ldg(&w_dpv[d * 16 + c]);
        }
        float m = l[0];
#pragma unroll
        for (int c = 1; c < 16; c++) m = fmaxf(m, l[c]);
        float s = 0.f;
#pragma unroll
        for (int c = 0; c < 16; c++) { l[c] = expf(l[c] - m); s += l[c]; }
        float inv = 1.f / s;
#pragma unroll
        for (int c = 0; c < 16; c++) sP[tid][c] = l[c] * inv;
    }
    __syncthreads();

#pragma unroll
    for (int r = 0; r < 4; r++) {
        int i = tid + (r << 7);
        int c = i >> 5, d = i & 31;
        float acc = 0.f;
#pragma unroll 8
        for (int e = 0; e < 64; e++) acc += sP[e][c] * sV[e][d];
        sVdp[c][d] = acc;
    }
#pragma unroll
    for (int r = 0; r < 4; r++) {
        int i = tid + (r << 7);
        int g = i >> 5, d = i & 31;
        float acc = 0.f;
        for (int a = 0; a <= g; a++) acc += __ldg(&E[g * 64 + a]) * sKdp[a][d];
        sEK[g][d] = acc;
    }
    __syncthreads();

    if (tid < 64) {
        const int e = tid;
        float st[16];
#pragma unroll
        for (int c = 0; c < 16; c++) {
            float acc = 0.f;
#pragma unroll
            for (int d = 0; d < 32; d++) acc += sEQ[e][d] * sEK[c][d];
            st[c] = acc * 5.656854249492381f;
        }
        float m = st[0];
#pragma unroll
        for (int c = 1; c < 16; c++) m = fmaxf(m, st[c]);
        float s = 0.f;
#pragma unroll
        for (int c = 0; c < 16; c++) { st[c] = expf(st[c] - m); s += st[c]; }
        float inv = 1.f / s;
#pragma unroll
        for (int c = 0; c < 16; c++) st[c] *= inv;
#pragma unroll
        for (int d = 0; d < 32; d++) {
            float acc = 0.f;
#pragma unroll
            for (int c = 0; c < 16; c++) acc += st[c] * sVdp[c][d];
            sEQ[e][d] = acc;
        }
    } else {
        const int idx = tid - 64;
        const int e = idx >> 1, h = idx & 1;
        float sh[16];
#pragma unroll
        for (int j = 0; j < 16; j++) {
            const int f = (h << 4) + j;
            float acc = 0.f;
#pragma unroll 8
            for (int a = 0; a < 64; a++) acc += sQ[a][e] * sK[a][f];
            sh[j] = acc * 8.0f;
        }
        float m = sh[0];
#pragma unroll
        for (int j = 1; j < 16; j++) m = fmaxf(m, sh[j]);
        m = fmaxf(m, __shfl_xor_sync(0xffffffffu, m, 1));
        float s = 0.f;
#pragma unroll
        for (int j = 0; j < 16; j++) { sh[j] = expf(sh[j] - m); s += sh[j]; }
        s += __shfl_xor_sync(0xffffffffu, s, 1);
        float inv = 1.f / s;
#pragma unroll
        for (int j = 0; j < 16; j++) sH[e][(h << 4) + j] = sh[j] * inv;
    }
    __syncthreads();

    float* otp = g_ot + (size_t)u * 2048;
    float* ohp = g_oh + (size_t)u * 2048;
#pragma unroll
    for (int r = 0; r < 16; r++) {
        int i = tid + (r << 7);
        int a = i >> 5, e = i & 31;
        otp[i] = sEQ[a][e];
        float acc = 0.f;
#pragma unroll
        for (int f = 0; f < 32; f++) acc += sH[e][f] * sV[a][f];
        ohp[i] = acc;
    }
}

// ======================= BN statistics (deterministic two-stage) =======================
__global__ void __launch_bounds__(256) k_bn_partial(int slot)
{
    const float* x = (slot == 0) ? g_ot : (slot == 1) ? g_oh : g_pre;
    const int c = threadIdx.x;
    const size_t base = (size_t)blockIdx.x * 65536;
    float s = 0.f, q = 0.f;
    for (int r = 0; r < 256; r++) {
        float v = x[base + (size_t)(r << 8) + c];
        s += v;
        q += v * v;
    }
    g_psum[slot * 65536 + (blockIdx.x << 8) + c] = s;
    g_psq [slot * 65536 + (blockIdx.x << 8) + c] = q;
}

__global__ void __launch_bounds__(256) k_bn_finalize(
    int slot, const float* __restrict__ g, const float* __restrict__ b)
{
    const int c = threadIdx.x;
    const float* ps = g_psum + slot * 65536;
    const float* pq = g_psq  + slot * 65536;
    float s = 0.f, q = 0.f;
    for (int i = 0; i < 256; i++) { s += ps[(i << 8) + c]; q += pq[(i << 8) + c]; }
    const float inv = 1.f / 65536.f;
    float mean = s * inv;
    float var  = q * inv - mean * mean;
    float rstd = rsqrtf(var + 1e-5f);
    float sc = g[c] * rstd;
    g_S[slot * 256 + c] = sc;
    g_T[slot * 256 + c] = b[c] - mean * sc;
}

// ======================= Final BN apply =======================
__global__ void __launch_bounds__(256) k_bn_apply(float* __restrict__ out)
{
    const size_t i = (size_t)blockIdx.x * 256 + threadIdx.x;
    float4 v = ((const float4*)g_pre)[i];
    const int c = (int)((i & 63) << 2);
    const float* S = g_S + 512;
    const float* T = g_T + 512;
    v.x = v.x * S[c + 0] + T[c + 0];
    v.y = v.y * S[c + 1] + T[c + 1];
    v.z = v.z * S[c + 2] + T[c + 2];
    v.w = v.w * S[c + 3] + T[c + 3];
    ((float4*)out)[i] = v;
}

// ======================= launch =======================
extern "C" void kernel_launch(void* const* d_in, const int* in_sizes, int n_in,
                              void* d_out, int out_size)
{
    const float* src    = (const float*)d_in[0];
    const float* ema    = (const float*)d_in[1];
    const float* w_qkv  = (const float*)d_in[2];
    const float* b_qkv  = (const float*)d_in[3];
    const float* w_dpk  = (const float*)d_in[4];
    const float* b_dpk  = (const float*)d_in[5];
    const float* w_dpv  = (const float*)d_in[6];
    const float* b_dpv  = (const float*)d_in[7];
    const float* bn1_g  = (const float*)d_in[8];
    const float* bn1_b  = (const float*)d_in[9];
    const float* bn2_g  = (const float*)d_in[10];
    const float* bn2_b  = (const float*)d_in[11];
    const float* bna_g  = (const float*)d_in[12];
    const float* bna_b  = (const float*)d_in[13];
    const float* ff1_w1 = (const float*)d_in[14];
    const float* ff1_b1 = (const float*)d_in[15];
    const float* ff1_w2 = (const float*)d_in[16];
    const float* ff1_b2 = (const float*)d_in[17];
    const float* ff2_w1 = (const float*)d_in[18];
    const float* ff2_b1 = (const float*)d_in[19];
    const float* ff2_w2 = (const float*)d_in[20];
    const float* ff2_b2 = (const float*)d_in[21];
    float* out = (float*)d_out;

    k_gemm_qkv_tc<<<dim3(N_QKV / 128, M_TOK / 128), 256>>>(src, w_qkv, b_qkv);
    k_attn<<<NUNITS, 128>>>(ema, w_dpk, b_dpk, w_dpv, b_dpv);
    k_bn_partial<<<256, 256>>>(0);
    k_bn_partial<<<256, 256>>>(1);
    k_bn_finalize<<<1, 256>>>(0, bn1_g, bn1_b);
    k_bn_finalize<<<1, 256>>>(1, bn2_g, bn2_b);
    k_ff1_tc<<<dim3(D_FF / 128, M_TOK / 128, 2), 256>>>(ff1_w1, ff2_w1, ff1_b1, ff2_b1);
    k_gemm2_tc<<<dim3(C_DIM / 128, M_TOK / 128), 256>>>(ff1_w2, ff2_w2, ff1_b2, ff2_b2, src);
    k_bn_partial<<<256, 256>>>(2);
    k_bn_finalize<<<1, 256>>>(2, bna_g, bna_b);
    k_bn_apply<<<(M_TOK * C_DIM / 4) / 256, 256>>>(out);
}

// round 7
// speedup vs baseline: 1.6091x; 1.3404x over previous
#include <cuda_runtime.h>
#include <cuda_bf16.h>
#include <math.h>
#include <stdint.h>

// Problem constants
#define M_TOK   65536          // B*nvars*H
#define C_DIM   256
#define N_QKV   768
#define D_FF    512
#define NUNITS  8192

// ---------------- scratch ----------------
__device__ float g_qkv[(size_t)M_TOK * N_QKV];
__device__ float g_ot [(size_t)M_TOK * C_DIM];
__device__ float g_oh [(size_t)M_TOK * C_DIM];
__device__ float g_h  [2ull * M_TOK * D_FF];
__device__ float g_pre[(size_t)M_TOK * C_DIM];
__device__ float g_psum[3 * 256 * 256];
__device__ float g_psq [3 * 256 * 256];
__device__ float g_S[3 * 256];
__device__ float g_T[3 * 256];
__device__ float g_wT[720896];      // transposed weights
#define WQKV_T 0
#define W1A_T  196608
#define W1B_T  327680
#define W2A_T  458752
#define W2B_T  589824

// ---------------- mma/ldmatrix helpers ----------------
__device__ __forceinline__ void mma16(float* d, const uint32_t* a, const uint32_t* b) {
    asm volatile(
        "mma.sync.aligned.m16n8k16.row.col.f32.bf16.bf16.f32 "
        "{%0,%1,%2,%3},{%4,%5,%6,%7},{%8,%9},{%0,%1,%2,%3};"
        : "+f"(d[0]), "+f"(d[1]), "+f"(d[2]), "+f"(d[3])
        : "r"(a[0]), "r"(a[1]), "r"(a[2]), "r"(a[3]), "r"(b[0]), "r"(b[1]));
}
__device__ __forceinline__ void ldx4(uint32_t* r, uint32_t a) {
    asm volatile("ldmatrix.sync.aligned.m8n8.x4.shared.b16 {%0,%1,%2,%3}, [%4];"
        : "=r"(r[0]), "=r"(r[1]), "=r"(r[2]), "=r"(r[3]) : "r"(a));
}

// ---- hi/lo bf16 split + pack 8 floats -> 2x uint4 ----
#define PACK8(p_, h4_, l4_) { \
    unsigned short hu_[8], lu_[8]; \
    _Pragma("unroll") for (int q_ = 0; q_ < 8; q_++) { \
        __nv_bfloat16 h_ = __float2bfloat16(p_[q_]); \
        float hf_ = __bfloat162float(h_); \
        __nv_bfloat16 l_ = __float2bfloat16(p_[q_] - hf_); \
        hu_[q_] = __bfloat16_as_ushort(h_); lu_[q_] = __bfloat16_as_ushort(l_); } \
    h4_.x = hu_[0] | ((uint32_t)hu_[1] << 16); h4_.y = hu_[2] | ((uint32_t)hu_[3] << 16); \
    h4_.z = hu_[4] | ((uint32_t)hu_[5] << 16); h4_.w = hu_[6] | ((uint32_t)hu_[7] << 16); \
    l4_.x = lu_[0] | ((uint32_t)lu_[1] << 16); l4_.y = lu_[2] | ((uint32_t)lu_[3] << 16); \
    l4_.z = lu_[4] | ((uint32_t)lu_[5] << 16); l4_.w = lu_[6] | ((uint32_t)lu_[7] << 16); }

// SMEM: [stage][AsH,AsL,BsH,BsL][4KB]. Tile-major ldmatrix-ready layout:
// 16x16 bf16 tile = 4 contiguous 8x8 submatrices (order: (r0-7,k0-7),(r8-15,k0-7),
// (r0-7,k8-15),(r8-15,k8-15)) = 512B. ldmatrix.x4 addr = tilebase + lane*16.
#define GEMM_PROLOG() \
    const int tid = threadIdx.x, lane = tid & 31, w = tid >> 5; \
    const int gid = lane >> 2, tig = lane & 3; \
    const int mt0 = (w >> 2) * 4, nt0 = (w & 3) * 2; \
    const int m_off = mt0 * 16, n_off = nt0 * 16; \
    const int cRow = blockIdx.y << 7, cCol = blockIdx.x << 7; \
    const int lr = tid >> 1, kh = tid & 1; \
    const int a_g = ((lr >> 4) << 5) + ((kh * 2 + ((lr & 15) >> 3)) << 3) + (lr & 7); \
    const uint32_t smb = (uint32_t)__cvta_generic_to_shared(sm); \
    float pa[8], pb[8]; \
    float acc[4][4][4]; \
    _Pragma("unroll") for (int i = 0; i < 4; i++) \
    _Pragma("unroll") for (int j = 0; j < 4; j++) \
    _Pragma("unroll") for (int r = 0; r < 4; r++) acc[i][j][r] = 0.f;

#define CVT_STORE(stg) { \
    uint4 h4_, l4_; \
    PACK8(pa, h4_, l4_); \
    ((uint4*)(&sm[stg][0][0]))[a_g] = h4_; \
    ((uint4*)(&sm[stg][1][0]))[a_g] = l4_; \
    PACK8(pb, h4_, l4_); \
    ((uint4*)(&sm[stg][2][0]))[a_g] = h4_; \
    ((uint4*)(&sm[stg][3][0]))[a_g] = l4_; }

#define COMPUTE_TILE(stg) { \
    const uint32_t bAH = smb + (stg) * 16384 + (uint32_t)lane * 16; \
    uint32_t aH[4][4], aL[4][4], bH[2][4], bL[2][4]; \
    _Pragma("unroll") for (int i = 0; i < 4; i++) { \
        ldx4(aH[i], bAH + (mt0 + i) * 512); \
        ldx4(aL[i], bAH + 4096 + (mt0 + i) * 512); } \
    _Pragma("unroll") for (int j2 = 0; j2 < 2; j2++) { \
        ldx4(bH[j2], bAH + 8192  + (nt0 + j2) * 512); \
        ldx4(bL[j2], bAH + 12288 + (nt0 + j2) * 512); } \
    _Pragma("unroll") for (int i = 0; i < 4; i++) \
    _Pragma("unroll") for (int j = 0; j < 4; j++) { \
        const int j2_ = j >> 1, g_ = j & 1; \
        uint32_t bh_[2] = {bH[j2_][g_], bH[j2_][g_ + 2]}; \
        uint32_t bl_[2] = {bL[j2_][g_], bL[j2_][g_ + 2]}; \
        mma16(acc[i][j], aH[i], bl_); \
        mma16(acc[i][j], aL[i], bh_); \
        mma16(acc[i][j], aH[i], bh_); } }

#define GEMM_LOOP(LOADM) \
    LOADM(0); CVT_STORE(0); \
    __syncthreads(); \
    { int p = 0; \
      for (int it = 0; it < NIT; it++) { \
        if (it + 1 < NIT) LOADM(it + 1); \
        COMPUTE_TILE(p); \
        if (it + 1 < NIT) CVT_STORE(p ^ 1); \
        __syncthreads(); \
        p ^= 1; } }

// ======================= weight transpose into g_wT: out[n][k] = in[k][n] =======================
// Writes g_wT + out_off directly (no cudaGetSymbolAddress needed host-side).
__global__ void k_transpose(const float* __restrict__ in, int out_off, int K, int N)
{
    __shared__ float t[32][33];
    float* out = g_wT + out_off;
    const int bx = blockIdx.x * 32, by = blockIdx.y * 32;
    const int x = threadIdx.x, y = threadIdx.y;
#pragma unroll
    for (int dy = 0; dy < 32; dy += 8)
        t[y + dy][x] = in[(size_t)(by + y + dy) * N + bx + x];
    __syncthreads();
#pragma unroll
    for (int dy = 0; dy < 32; dy += 8)
        out[(size_t)(bx + y + dy) * K + by + x] = t[x][y + dy];
}

// ======================= GEMM 1: qkv = src @ w_qkv + b_qkv =======================
__global__ void __launch_bounds__(256) k_gemm_qkv_tc(
    const float* __restrict__ A, const float* __restrict__ bias)
{
    constexpr int NIT = 256 / 16;
    __shared__ __align__(16) uint32_t sm[2][4][1024];
    const float* WT = g_wT + WQKV_T;
    GEMM_PROLOG();

#define QKV_LD(it) { \
    const float* pA_ = A + (size_t)(cRow + lr) * 256 + (it) * 16 + kh * 8; \
    float4 v_ = *(const float4*)pA_; \
    pa[0] = v_.x; pa[1] = v_.y; pa[2] = v_.z; pa[3] = v_.w; \
    v_ = *(const float4*)(pA_ + 4); \
    pa[4] = v_.x; pa[5] = v_.y; pa[6] = v_.z; pa[7] = v_.w; \
    const float* pB_ = WT + (size_t)(cCol + lr) * 256 + (it) * 16 + kh * 8; \
    v_ = *(const float4*)pB_; \
    pb[0] = v_.x; pb[1] = v_.y; pb[2] = v_.z; pb[3] = v_.w; \
    v_ = *(const float4*)(pB_ + 4); \
    pb[4] = v_.x; pb[5] = v_.y; pb[6] = v_.z; pb[7] = v_.w; }

    GEMM_LOOP(QKV_LD);

#pragma unroll
    for (int i = 0; i < 4; i++)
#pragma unroll
        for (int j = 0; j < 4; j++) {
            int row0 = cRow + m_off + i * 16 + gid;
            int col  = cCol + n_off + j * 8 + tig * 2;
            float b0 = bias[col], b1 = bias[col + 1];
            float2 v0 = {acc[i][j][0] + b0, acc[i][j][1] + b1};
            float2 v1 = {acc[i][j][2] + b0, acc[i][j][3] + b1};
            *(float2*)&g_qkv[(size_t)row0 * N_QKV + col] = v0;
            *(float2*)&g_qkv[(size_t)(row0 + 8) * N_QKV + col] = v1;
        }
}

// ======================= GEMM 2: h = gelu(BN(o) @ W1 + b1) =======================
__global__ void __launch_bounds__(256) k_ff1_tc(
    const float* __restrict__ b1a, const float* __restrict__ b1b)
{
    constexpr int NIT = 256 / 16;
    __shared__ __align__(16) uint32_t sm[2][4][1024];
    __shared__ float sS[256], sT[256];

    const int bz = blockIdx.z;
    const float* A    = bz ? g_oh : g_ot;
    const float* WT   = g_wT + (bz ? W1B_T : W1A_T);
    const float* bias = bz ? b1b : b1a;
    float* Cout = g_h + (size_t)bz * ((size_t)M_TOK * D_FF);

    GEMM_PROLOG();
    sS[tid] = g_S[bz * 256 + tid];
    sT[tid] = g_T[bz * 256 + tid];
    __syncthreads();

#define FF1_LD(it) { \
    const int kb_ = (it) * 16 + kh * 8; \
    const float* pA_ = A + (size_t)(cRow + lr) * 256 + kb_; \
    float4 v_ = *(const float4*)pA_; \
    pa[0] = v_.x * sS[kb_+0] + sT[kb_+0]; pa[1] = v_.y * sS[kb_+1] + sT[kb_+1]; \
    pa[2] = v_.z * sS[kb_+2] + sT[kb_+2]; pa[3] = v_.w * sS[kb_+3] + sT[kb_+3]; \
    v_ = *(const float4*)(pA_ + 4); \
    pa[4] = v_.x * sS[kb_+4] + sT[kb_+4]; pa[5] = v_.y * sS[kb_+5] + sT[kb_+5]; \
    pa[6] = v_.z * sS[kb_+6] + sT[kb_+6]; pa[7] = v_.w * sS[kb_+7] + sT[kb_+7]; \
    const float* pB_ = WT + (size_t)(cCol + lr) * 256 + (it) * 16 + kh * 8; \
    v_ = *(const float4*)pB_; \
    pb[0] = v_.x; pb[1] = v_.y; pb[2] = v_.z; pb[3] = v_.w; \
    v_ = *(const float4*)(pB_ + 4); \
    pb[4] = v_.x; pb[5] = v_.y; pb[6] = v_.z; pb[7] = v_.w; }

    GEMM_LOOP(FF1_LD);

#pragma unroll
    for (int i = 0; i < 4; i++)
#pragma unroll
        for (int j = 0; j < 4; j++) {
            int row0 = cRow + m_off + i * 16 + gid;
            int col  = cCol + n_off + j * 8 + tig * 2;
            float b0 = bias[col], b1 = bias[col + 1];
            float x0 = acc[i][j][0] + b0, x1 = acc[i][j][1] + b1;
            float x2 = acc[i][j][2] + b0, x3 = acc[i][j][3] + b1;
            float2 v0, v1;
            v0.x = 0.5f * x0 * (1.f + erff(x0 * 0.70710678118654752f));
            v0.y = 0.5f * x1 * (1.f + erff(x1 * 0.70710678118654752f));
            v1.x = 0.5f * x2 * (1.f + erff(x2 * 0.70710678118654752f));
            v1.y = 0.5f * x3 * (1.f + erff(x3 * 0.70710678118654752f));
            *(float2*)&Cout[(size_t)row0 * D_FF + col] = v0;
            *(float2*)&Cout[(size_t)(row0 + 8) * D_FF + col] = v1;
        }
}

// ======================= GEMM 3: pre = src + h1@W2a + h2@W2b + biases =======================
__global__ void __launch_bounds__(256) k_gemm2_tc(
    const float* __restrict__ b2a, const float* __restrict__ b2b,
    const float* __restrict__ src)
{
    constexpr int NIT = 64;   // 2 branches x 512/16
    __shared__ __align__(16) uint32_t sm[2][4][1024];
    GEMM_PROLOG();

#define G2_LD(it) { \
    const int pp_ = (it) >> 5, k0_ = ((it) & 31) * 16 + kh * 8; \
    const float* pA_ = g_h + (size_t)pp_ * ((size_t)M_TOK * D_FF) \
                       + (size_t)(cRow + lr) * 512 + k0_; \
    float4 v_ = *(const float4*)pA_; \
    pa[0] = v_.x; pa[1] = v_.y; pa[2] = v_.z; pa[3] = v_.w; \
    v_ = *(const float4*)(pA_ + 4); \
    pa[4] = v_.x; pa[5] = v_.y; pa[6] = v_.z; pa[7] = v_.w; \
    const float* pB_ = g_wT + (pp_ ? W2B_T : W2A_T) \
                       + (size_t)(cCol + lr) * 512 + k0_; \
    v_ = *(const float4*)pB_; \
    pb[0] = v_.x; pb[1] = v_.y; pb[2] = v_.z; pb[3] = v_.w; \
    v_ = *(const float4*)(pB_ + 4); \
    pb[4] = v_.x; pb[5] = v_.y; pb[6] = v_.z; pb[7] = v_.w; }

    GEMM_LOOP(G2_LD);

#pragma unroll
    for (int i = 0; i < 4; i++)
#pragma unroll
        for (int j = 0; j < 4; j++) {
            int row0 = cRow + m_off + i * 16 + gid;
            int col  = cCol + n_off + j * 8 + tig * 2;
            float b0 = b2a[col] + b2b[col], b1 = b2a[col + 1] + b2b[col + 1];
            float2 s0 = *(const float2*)&src[(size_t)row0 * C_DIM + col];
            float2 s1 = *(const float2*)&src[(size_t)(row0 + 8) * C_DIM + col];
            float2 v0 = {acc[i][j][0] + b0 + s0.x, acc[i][j][1] + b1 + s0.y};
            float2 v1 = {acc[i][j][2] + b0 + s1.x, acc[i][j][3] + b1 + s1.y};
            *(float2*)&g_pre[(size_t)row0 * C_DIM + col] = v0;
            *(float2*)&g_pre[(size_t)(row0 + 8) * C_DIM + col] = v1;
        }
}

// ======================= Attention: one block per (b,n,head) unit =======================
__global__ void __launch_bounds__(128) k_attn(
    const float* __restrict__ E,
    const float* __restrict__ w_dpk, const float* __restrict__ b_dpk,
    const float* __restrict__ w_dpv, const float* __restrict__ b_dpv)
{
    __shared__ float sQ[64][33], sK[64][33], sV[64][33];
    __shared__ float sP[64][16];
    __shared__ float sKdp[16][32], sVdp[16][32];
    __shared__ float sEQ[64][33];
    __shared__ float sEK[16][32];
    __shared__ float sH[32][33];

    const int u    = blockIdx.x;
    const int head = u & 7;
    const int bn   = u >> 3;
    const int tid  = threadIdx.x;

    const float* base = g_qkv + (size_t)bn * (64 * N_QKV) + head * 32;
    for (int i = tid; i < 2048; i += 128) {
        int e = i >> 5, d = i & 31;
        const float* p = base + e * N_QKV + d;
        sQ[e][d] = p[0];
        sK[e][d] = p[256];
        sV[e][d] = p[512];
    }
    __syncthreads();

    if (tid < 64) {
        float l[16];
#pragma unroll
        for (int c = 0; c < 16; c++) l[c] = __ldg(&b_dpk[c]);
#pragma unroll 8
        for (int d = 0; d < 32; d++) {
            float kv = sK[tid][d];
#pragma unroll
            for (int c = 0; c < 16; c++) l[c] += kv * __ldg(&w_dpk[d * 16 + c]);
        }
        float m = l[0];
#pragma unroll
        for (int c = 1; c < 16; c++) m = fmaxf(m, l[c]);
        float s = 0.f;
#pragma unroll
        for (int c = 0; c < 16; c++) { l[c] = expf(l[c] - m); s += l[c]; }
        float inv = 1.f / s;
#pragma unroll
        for (int c = 0; c < 16; c++) sP[tid][c] = l[c] * inv;
    }
    __syncthreads();

#pragma unroll
    for (int r = 0; r < 4; r++) {
        int i = tid + (r << 7);
        int c = i >> 5, d = i & 31;
        float acc = 0.f;
#pragma unroll 8
        for (int e = 0; e < 64; e++) acc += sP[e][c] * sK[e][d];
        sKdp[c][d] = acc;
    }
#pragma unroll
    for (int r = 0; r < 16; r++) {
        int i = tid + (r << 7);
        int g = i >> 5, d = i & 31;
        float acc = 0.f;
        for (int a = 0; a <= g; a++) acc += __ldg(&E[g * 64 + a]) * sQ[a][d];
        sEQ[g][d] = acc;
    }
    __syncthreads();

    if (tid < 64) {
        float l[16];
#pragma unroll
        for (int c = 0; c < 16; c++) l[c] = __ldg(&b_dpv[c]);
#pragma unroll 8
        for (int d = 0; d < 32; d++) {
            float vv = sV[tid][d];
#pragma unroll
            for (int c = 0; c < 16; c++) l[c] += vv * __ldg(&w_dpv[d * 16 + c]);
        }
        float m = l[0];
#pragma unroll
        for (int c = 1; c < 16; c++) m = fmaxf(m, l[c]);
        float s = 0.f;
#pragma unroll
        for (int c = 0; c < 16; c++) { l[c] = expf(l[c] - m); s += l[c]; }
        float inv = 1.f / s;
#pragma unroll
        for (int c = 0; c < 16; c++) sP[tid][c] = l[c] * inv;
    }
    __syncthreads();

#pragma unroll
    for (int r = 0; r < 4; r++) {
        int i = tid + (r << 7);
        int c = i >> 5, d = i & 31;
        float acc = 0.f;
#pragma unroll 8
        for (int e = 0; e < 64; e++) acc += sP[e][c] * sV[e][d];
        sVdp[c][d] = acc;
    }
#pragma unroll
    for (int r = 0; r < 4; r++) {
        int i = tid + (r << 7);
        int g = i >> 5, d = i & 31;
        float acc = 0.f;
        for (int a = 0; a <= g; a++) acc += __ldg(&E[g * 64 + a]) * sKdp[a][d];
        sEK[g][d] = acc;
    }
    __syncthreads();

    if (tid < 64) {
        const int e = tid;
        float st[16];
#pragma unroll
        for (int c = 0; c < 16; c++) {
            float acc = 0.f;
#pragma unroll
            for (int d = 0; d < 32; d++) acc += sEQ[e][d] * sEK[c][d];
            st[c] = acc * 5.656854249492381f;
        }
        float m = st[0];
#pragma unroll
        for (int c = 1; c < 16; c++) m = fmaxf(m, st[c]);
        float s = 0.f;
#pragma unroll
        for (int c = 0; c < 16; c++) { st[c] = expf(st[c] - m); s += st[c]; }
        float inv = 1.f / s;
#pragma unroll
        for (int c = 0; c < 16; c++) st[c] *= inv;
#pragma unroll
        for (int d = 0; d < 32; d++) {
            float acc = 0.f;
#pragma unroll
            for (int c = 0; c < 16; c++) acc += st[c] * sVdp[c][d];
            sEQ[e][d] = acc;
        }
    } else {
        const int idx = tid - 64;
        const int e = idx >> 1, h = idx & 1;
        float sh[16];
#pragma unroll
        for (int j = 0; j < 16; j++) {
            const int f = (h << 4) + j;
            float acc = 0.f;
#pragma unroll 8
            for (int a = 0; a < 64; a++) acc += sQ[a][e] * sK[a][f];
            sh[j] = acc * 8.0f;
        }
        float m = sh[0];
#pragma unroll
        for (int j = 1; j < 16; j++) m = fmaxf(m, sh[j]);
        m = fmaxf(m, __shfl_xor_sync(0xffffffffu, m, 1));
        float s = 0.f;
#pragma unroll
        for (int j = 0; j < 16; j++) { sh[j] = expf(sh[j] - m); s += sh[j]; }
        s += __shfl_xor_sync(0xffffffffu, s, 1);
        float inv = 1.f / s;
#pragma unroll
        for (int j = 0; j < 16; j++) sH[e][(h << 4) + j] = sh[j] * inv;
    }
    __syncthreads();

    float* otp = g_ot + (size_t)u * 2048;
    float* ohp = g_oh + (size_t)u * 2048;
#pragma unroll
    for (int r = 0; r < 16; r++) {
        int i = tid + (r << 7);
        int a = i >> 5, e = i & 31;
        otp[i] = sEQ[a][e];
        float acc = 0.f;
#pragma unroll
        for (int f = 0; f < 32; f++) acc += sH[e][f] * sV[a][f];
        ohp[i] = acc;
    }
}

// ======================= BN statistics (deterministic two-stage) =======================
__global__ void __launch_bounds__(256) k_bn_partial(int slot)
{
    const float* x = (slot == 0) ? g_ot : (slot == 1) ? g_oh : g_pre;
    const int c = threadIdx.x;
    const size_t base = (size_t)blockIdx.x * 65536;
    float s = 0.f, q = 0.f;
    for (int r = 0; r < 256; r++) {
        float v = x[base + (size_t)(r << 8) + c];
        s += v;
        q += v * v;
    }
    g_psum[slot * 65536 + (blockIdx.x << 8) + c] = s;
    g_psq [slot * 65536 + (blockIdx.x << 8) + c] = q;
}

__global__ void __launch_bounds__(256) k_bn_finalize(
    int slot, const float* __restrict__ g, const float* __restrict__ b)
{
    const int c = threadIdx.x;
    const float* ps = g_psum + slot * 65536;
    const float* pq = g_psq  + slot * 65536;
    float s = 0.f, q = 0.f;
    for (int i = 0; i < 256; i++) { s += ps[(i << 8) + c]; q += pq[(i << 8) + c]; }
    const float inv = 1.f / 65536.f;
    float mean = s * inv;
    float var  = q * inv - mean * mean;
    float rstd = rsqrtf(var + 1e-5f);
    float sc = g[c] * rstd;
    g_S[slot * 256 + c] = sc;
    g_T[slot * 256 + c] = b[c] - mean * sc;
}

// ======================= Final BN apply =======================
__global__ void __launch_bounds__(256) k_bn_apply(float* __restrict__ out)
{
    const size_t i = (size_t)blockIdx.x * 256 + threadIdx.x;
    float4 v = ((const float4*)g_pre)[i];
    const int c = (int)((i & 63) << 2);
    const float* S = g_S + 512;
    const float* T = g_T + 512;
    v.x = v.x * S[c + 0] + T[c + 0];
    v.y = v.y * S[c + 1] + T[c + 1];
    v.z = v.z * S[c + 2] + T[c + 2];
    v.w = v.w * S[c + 3] + T[c + 3];
    ((float4*)out)[i] = v;
}

// ======================= launch =======================
extern "C" void kernel_launch(void* const* d_in, const int* in_sizes, int n_in,
                              void* d_out, int out_size)
{
    const float* src    = (const float*)d_in[0];
    const float* ema    = (const float*)d_in[1];
    const float* w_qkv  = (const float*)d_in[2];
    const float* b_qkv  = (const float*)d_in[3];
    const float* w_dpk  = (const float*)d_in[4];
    const float* b_dpk  = (const float*)d_in[5];
    const float* w_dpv  = (const float*)d_in[6];
    const float* b_dpv  = (const float*)d_in[7];
    const float* bn1_g  = (const float*)d_in[8];
    const float* bn1_b  = (const float*)d_in[9];
    const float* bn2_g  = (const float*)d_in[10];
    const float* bn2_b  = (const float*)d_in[11];
    const float* bna_g  = (const float*)d_in[12];
    const float* bna_b  = (const float*)d_in[13];
    const float* ff1_w1 = (const float*)d_in[14];
    const float* ff1_b1 = (const float*)d_in[15];
    const float* ff1_w2 = (const float*)d_in[16];
    const float* ff1_b2 = (const float*)d_in[17];
    const float* ff2_w1 = (const float*)d_in[18];
    const float* ff2_b1 = (const float*)d_in[19];
    const float* ff2_w2 = (const float*)d_in[20];
    const float* ff2_b2 = (const float*)d_in[21];
    float* out = (float*)d_out;

    // one-time weight transposes (deterministic every call; write g_wT directly)
    k_transpose<<<dim3(24,  8), dim3(32, 8)>>>(w_qkv,  WQKV_T, 256, 768);
    k_transpose<<<dim3(16,  8), dim3(32, 8)>>>(ff1_w1, W1A_T,  256, 512);
    k_transpose<<<dim3(16,  8), dim3(32, 8)>>>(ff2_w1, W1B_T,  256, 512);
    k_transpose<<<dim3( 8, 16), dim3(32, 8)>>>(ff1_w2, W2A_T,  512, 256);
    k_transpose<<<dim3( 8, 16), dim3(32, 8)>>>(ff2_w2, W2B_T,  512, 256);

    k_gemm_qkv_tc<<<dim3(N_QKV / 128, M_TOK / 128), 256>>>(src, b_qkv);
    k_attn<<<NUNITS, 128>>>(ema, w_dpk, b_dpk, w_dpv, b_dpv);
    k_bn_partial<<<256, 256>>>(0);
    k_bn_partial<<<256, 256>>>(1);
    k_bn_finalize<<<1, 256>>>(0, bn1_g, bn1_b);
    k_bn_finalize<<<1, 256>>>(1, bn2_g, bn2_b);
    k_ff1_tc<<<dim3(D_FF / 128, M_TOK / 128, 2), 256>>>(ff1_b1, ff2_b1);
    k_gemm2_tc<<<dim3(C_DIM / 128, M_TOK / 128), 256>>>(ff1_b2, ff2_b2, src);
    k_bn_partial<<<256, 256>>>(2);
    k_bn_finalize<<<1, 256>>>(2, bna_g, bna_b);
    k_bn_apply<<<(M_TOK * C_DIM / 4) / 256, 256>>>(out);
}

// round 10
// speedup vs baseline: 1.6828x; 1.0458x over previous
#include <cuda_runtime.h>
#include <cuda_bf16.h>
#include <math.h>
#include <stdint.h>

// Problem constants
#define M_TOK   65536          // B*nvars*H
#define C_DIM   256
#define N_QKV   768
#define D_FF    512
#define NUNITS  8192

// ---------------- scratch ----------------
// Packed hi/lo format: uint32 = bf16(hi) | bf16(lo)<<16, hi+lo ~= fp32 value (~19 bits)
__device__ float    g_qkv[(size_t)M_TOK * N_QKV];          // f32 (attention input)
__device__ uint32_t g_src_hl[(size_t)M_TOK * C_DIM];       // packed src
__device__ uint32_t g_ot_hl [(size_t)M_TOK * C_DIM];       // packed out_tok
__device__ uint32_t g_oh_hl [(size_t)M_TOK * C_DIM];       // packed out_hid
__device__ uint32_t g_h_hl  [2ull * M_TOK * D_FF];         // packed FF hidden
__device__ float    g_pre[(size_t)M_TOK * C_DIM];
__device__ float    g_psum[3 * 256 * 256];
__device__ float    g_psq [3 * 256 * 256];
__device__ float    g_S[3 * 256];
__device__ float    g_T[3 * 256];
__device__ uint32_t g_whl[720896];   // packed transposed weights [N][K]
__device__ float    g_b1c[2 * 512]; // BN-folded ff1 bias
#define WQ_O  0
#define W1A_O 196608
#define W1B_O 327680
#define W2A_O 458752
#define W2B_O 589824

// ---------------- helpers ----------------
__device__ __forceinline__ uint32_t packhl(float v) {
    __nv_bfloat16 h = __float2bfloat16(v);
    float hf = __bfloat162float(h);
    __nv_bfloat16 l = __float2bfloat16(v - hf);
    return (uint32_t)__bfloat16_as_ushort(h) | ((uint32_t)__bfloat16_as_ushort(l) << 16);
}
__device__ __forceinline__ float unpackf(uint32_t p) {
    return __bfloat162float(__ushort_as_bfloat16((unsigned short)(p & 0xFFFF)))
         + __bfloat162float(__ushort_as_bfloat16((unsigned short)(p >> 16)));
}
__device__ __forceinline__ void mma16(float* d, const uint32_t* a, const uint32_t* b) {
    asm volatile(
        "mma.sync.aligned.m16n8k16.row.col.f32.bf16.bf16.f32 "
        "{%0,%1,%2,%3},{%4,%5,%6,%7},{%8,%9},{%0,%1,%2,%3};"
        : "+f"(d[0]), "+f"(d[1]), "+f"(d[2]), "+f"(d[3])
        : "r"(a[0]), "r"(a[1]), "r"(a[2]), "r"(a[3]), "r"(b[0]), "r"(b[1]));
}
__device__ __forceinline__ void ldx4(uint32_t* r, uint32_t a) {
    asm volatile("ldmatrix.sync.aligned.m8n8.x4.shared.b16 {%0,%1,%2,%3}, [%4];"
        : "=r"(r[0]), "=r"(r[1]), "=r"(r[2]), "=r"(r[3]) : "r"(a));
}

// Peel packed hi/lo planes: 8 packed u32 -> uint4 of 8 hi-bf16 + uint4 of 8 lo-bf16
#define UNPACK8(p_, h4_, l4_) { \
    h4_.x = __byte_perm(p_[0], p_[1], 0x5410); l4_.x = __byte_perm(p_[0], p_[1], 0x7632); \
    h4_.y = __byte_perm(p_[2], p_[3], 0x5410); l4_.y = __byte_perm(p_[2], p_[3], 0x7632); \
    h4_.z = __byte_perm(p_[4], p_[5], 0x5410); l4_.z = __byte_perm(p_[4], p_[5], 0x7632); \
    h4_.w = __byte_perm(p_[6], p_[7], 0x5410); l4_.w = __byte_perm(p_[6], p_[7], 0x7632); }

// SMEM: [stage][AsH,AsL,BsH,BsL][4KB]; 16x16 bf16 tile = 4 contiguous 8x8 (512B),
// ldmatrix.x4 addr = tilebase + lane*16.  (layout verified in R7)
#define GEMM_PROLOG() \
    const int tid = threadIdx.x, lane = tid & 31, w = tid >> 5; \
    const int gid = lane >> 2, tig = lane & 3; \
    const int mt0 = (w >> 2) * 4, nt0 = (w & 3) * 2; \
    const int m_off = mt0 * 16, n_off = nt0 * 16; \
    const int cRow = blockIdx.y << 7, cCol = blockIdx.x << 7; \
    const int lr = tid >> 1, kh = tid & 1; \
    const int a_g = ((lr >> 4) << 5) + ((kh * 2 + ((lr & 15) >> 3)) << 3) + (lr & 7); \
    const uint32_t smb = (uint32_t)__cvta_generic_to_shared(sm); \
    uint32_t pa[8], pb[8]; \
    float acc[4][4][4]; \
    _Pragma("unroll") for (int i = 0; i < 4; i++) \
    _Pragma("unroll") for (int j = 0; j < 4; j++) \
    _Pragma("unroll") for (int r = 0; r < 4; r++) acc[i][j][r] = 0.f;

#define CVT_STORE(stg) { \
    uint4 h4_, l4_; \
    UNPACK8(pa, h4_, l4_); \
    ((uint4*)(&sm[stg][0][0]))[a_g] = h4_; \
    ((uint4*)(&sm[stg][1][0]))[a_g] = l4_; \
    UNPACK8(pb, h4_, l4_); \
    ((uint4*)(&sm[stg][2][0]))[a_g] = h4_; \
    ((uint4*)(&sm[stg][3][0]))[a_g] = l4_; }

#define COMPUTE_TILE(stg) { \
    const uint32_t bAH = smb + (stg) * 16384 + (uint32_t)lane * 16; \
    uint32_t aH[4][4], aL[4][4], bH[2][4], bL[2][4]; \
    _Pragma("unroll") for (int i = 0; i < 4; i++) { \
        ldx4(aH[i], bAH + (mt0 + i) * 512); \
        ldx4(aL[i], bAH + 4096 + (mt0 + i) * 512); } \
    _Pragma("unroll") for (int j2 = 0; j2 < 2; j2++) { \
        ldx4(bH[j2], bAH + 8192  + (nt0 + j2) * 512); \
        ldx4(bL[j2], bAH + 12288 + (nt0 + j2) * 512); } \
    _Pragma("unroll") for (int i = 0; i < 4; i++) \
    _Pragma("unroll") for (int j = 0; j < 4; j++) { \
        const int j2_ = j >> 1, g_ = j & 1; \
        uint32_t bh_[2] = {bH[j2_][g_], bH[j2_][g_ + 2]}; \
        uint32_t bl_[2] = {bL[j2_][g_], bL[j2_][g_ + 2]}; \
        mma16(acc[i][j], aH[i], bl_); \
        mma16(acc[i][j], aL[i], bh_); \
        mma16(acc[i][j], aH[i], bh_); } }

#define GEMM_LOOP(LOADM) \
    LOADM(0); CVT_STORE(0); \
    __syncthreads(); \
    { int p = 0; \
      for (int it = 0; it < NIT; it++) { \
        if (it + 1 < NIT) LOADM(it + 1); \
        COMPUTE_TILE(p); \
        if (it + 1 < NIT) CVT_STORE(p ^ 1); \
        __syncthreads(); \
        p ^= 1; } }

// Packed operand loaders (8 consecutive K elements per thread)
#define HL_LDA(base, ld, it) { \
    const uint32_t* p_ = (base) + (size_t)(cRow + lr) * (ld) + (it) * 16 + kh * 8; \
    uint4 q0 = *(const uint4*)p_; uint4 q1 = *(const uint4*)(p_ + 4); \
    pa[0]=q0.x; pa[1]=q0.y; pa[2]=q0.z; pa[3]=q0.w; \
    pa[4]=q1.x; pa[5]=q1.y; pa[6]=q1.z; pa[7]=q1.w; }
#define HL_LDB(base, ld, it) { \
    const uint32_t* p_ = (base) + (size_t)(cCol + lr) * (ld) + (it) * 16 + kh * 8; \
    uint4 q0 = *(const uint4*)p_; uint4 q1 = *(const uint4*)(p_ + 4); \
    pb[0]=q0.x; pb[1]=q0.y; pb[2]=q0.z; pb[3]=q0.w; \
    pb[4]=q1.x; pb[5]=q1.y; pb[6]=q1.z; pb[7]=q1.w; }

// ======================= pre-pass: split src to packed =======================
__global__ void __launch_bounds__(256) k_split_src(const float* __restrict__ src)
{
    const size_t i = (size_t)blockIdx.x * 256 + threadIdx.x;   // float4 index
    float4 v = ((const float4*)src)[i];
    uint4 o;
    o.x = packhl(v.x); o.y = packhl(v.y); o.z = packhl(v.z); o.w = packhl(v.w);
    ((uint4*)g_src_hl)[i] = o;
}

// ======================= weight prep: transpose + optional BN-scale + split =======================
// in [K][N] f32 -> g_whl+out_off [N][K] packed.  s_off>=0: scale row k by g_S[s_off+k].
__global__ void k_prep_w(const float* __restrict__ in, int out_off, int K, int N, int s_off)
{
    __shared__ float t[32][33];
    uint32_t* out = g_whl + out_off;
    const int bx = blockIdx.x * 32, by = blockIdx.y * 32;   // bx over N, by over K
    const int x = threadIdx.x, y = threadIdx.y;
#pragma unroll
    for (int dy = 0; dy < 32; dy += 8) {
        float v = in[(size_t)(by + y + dy) * N + bx + x];
        if (s_off >= 0) v *= g_S[s_off + by + y + dy];
        t[y + dy][x] = v;
    }
    __syncthreads();
#pragma unroll
    for (int dy = 0; dy < 32; dy += 8)
        out[(size_t)(bx + y + dy) * K + by + x] = packhl(t[x][y + dy]);
}

// ======================= BN-folded ff1 bias: b1'[n] = b1[n] + sum_k T[k]*W1[k][n] =======================
__global__ void k_bias1(const float* __restrict__ w1a, const float* __restrict__ b1a,
                        const float* __restrict__ w1b, const float* __restrict__ b1b)
{
    const int z = blockIdx.x, n = threadIdx.x;   // 2 x 512
    const float* W = z ? w1b : w1a;
    const float* b = z ? b1b : b1a;
    const float* T = g_T + z * 256;
    float s = b[n];
    for (int k = 0; k < 256; k++) s += T[k] * W[(size_t)k * 512 + n];
    g_b1c[z * 512 + n] = s;
}

// ======================= GEMM 1: qkv = src @ w_qkv + b_qkv =======================
__global__ void __launch_bounds__(256) k_qkv_tc(const float* __restrict__ bias)
{
    constexpr int NIT = 16;
    __shared__ __align__(16) uint32_t sm[2][4][1024];
    GEMM_PROLOG();
    const uint32_t* WB = g_whl + WQ_O;
#define QKV_LD(it) { HL_LDA(g_src_hl, 256, it); HL_LDB(WB, 256, it); }
    GEMM_LOOP(QKV_LD);
#pragma unroll
    for (int i = 0; i < 4; i++)
#pragma unroll
        for (int j = 0; j < 4; j++) {
            int row0 = cRow + m_off + i * 16 + gid;
            int col  = cCol + n_off + j * 8 + tig * 2;
            float b0 = bias[col], b1 = bias[col + 1];
            float2 v0 = {acc[i][j][0] + b0, acc[i][j][1] + b1};
            float2 v1 = {acc[i][j][2] + b0, acc[i][j][3] + b1};
            *(float2*)&g_qkv[(size_t)row0 * N_QKV + col] = v0;
            *(float2*)&g_qkv[(size_t)(row0 + 8) * N_QKV + col] = v1;
        }
}

// ======================= GEMM 2: h = gelu(o @ W1' + b1') (BN folded into W1',b1') =======================
__global__ void __launch_bounds__(256) k_ff1_tc()
{
    constexpr int NIT = 16;
    __shared__ __align__(16) uint32_t sm[2][4][1024];
    GEMM_PROLOG();
    const int bz = blockIdx.z;
    const uint32_t* Ahl = bz ? g_oh_hl : g_ot_hl;
    const uint32_t* WB  = g_whl + (bz ? W1B_O : W1A_O);
    const float* bias   = g_b1c + bz * 512;
    uint32_t* Cout = g_h_hl + (size_t)bz * ((size_t)M_TOK * D_FF);
#define FF1_LD(it) { HL_LDA(Ahl, 256, it); HL_LDB(WB, 256, it); }
    GEMM_LOOP(FF1_LD);
#pragma unroll
    for (int i = 0; i < 4; i++)
#pragma unroll
        for (int j = 0; j < 4; j++) {
            int row0 = cRow + m_off + i * 16 + gid;
            int col  = cCol + n_off + j * 8 + tig * 2;
            float b0 = bias[col], b1 = bias[col + 1];
            float x0 = acc[i][j][0] + b0, x1 = acc[i][j][1] + b1;
            float x2 = acc[i][j][2] + b0, x3 = acc[i][j][3] + b1;
            float g0 = 0.5f * x0 * (1.f + erff(x0 * 0.70710678118654752f));
            float g1 = 0.5f * x1 * (1.f + erff(x1 * 0.70710678118654752f));
            float g2v = 0.5f * x2 * (1.f + erff(x2 * 0.70710678118654752f));
            float g3 = 0.5f * x3 * (1.f + erff(x3 * 0.70710678118654752f));
            uint2 u0 = {packhl(g0), packhl(g1)};
            uint2 u1 = {packhl(g2v), packhl(g3)};
            *(uint2*)&Cout[(size_t)row0 * D_FF + col] = u0;
            *(uint2*)&Cout[(size_t)(row0 + 8) * D_FF + col] = u1;
        }
}

// ======================= GEMM 3: pre = src + h1@W2a + h2@W2b + biases =======================
__global__ void __launch_bounds__(256) k_g2_tc(
    const float* __restrict__ b2a, const float* __restrict__ b2b,
    const float* __restrict__ src)
{
    constexpr int NIT = 64;   // 2 branches x 512/16
    __shared__ __align__(16) uint32_t sm[2][4][1024];
    GEMM_PROLOG();
#define G2_LD(it) { \
    const int pp_ = (it) >> 5, k0it_ = (it) & 31; \
    const uint32_t* Ahl_ = g_h_hl + (size_t)pp_ * ((size_t)M_TOK * D_FF); \
    const uint32_t* WB_  = g_whl + (pp_ ? W2B_O : W2A_O); \
    HL_LDA(Ahl_, 512, k0it_); HL_LDB(WB_, 512, k0it_); }
    GEMM_LOOP(G2_LD);
#pragma unroll
    for (int i = 0; i < 4; i++)
#pragma unroll
        for (int j = 0; j < 4; j++) {
            int row0 = cRow + m_off + i * 16 + gid;
            int col  = cCol + n_off + j * 8 + tig * 2;
            float b0 = b2a[col] + b2b[col], b1 = b2a[col + 1] + b2b[col + 1];
            float2 s0 = *(const float2*)&src[(size_t)row0 * C_DIM + col];
            float2 s1 = *(const float2*)&src[(size_t)(row0 + 8) * C_DIM + col];
            float2 v0 = {acc[i][j][0] + b0 + s0.x, acc[i][j][1] + b1 + s0.y};
            float2 v1 = {acc[i][j][2] + b0 + s1.x, acc[i][j][3] + b1 + s1.y};
            *(float2*)&g_pre[(size_t)row0 * C_DIM + col] = v0;
            *(float2*)&g_pre[(size_t)(row0 + 8) * C_DIM + col] = v1;
        }
}

// ======================= Attention: one block per (b,n,head) unit =======================
__global__ void __launch_bounds__(128) k_attn(
    const float* __restrict__ E,
    const float* __restrict__ w_dpk, const float* __restrict__ b_dpk,
    const float* __restrict__ w_dpv, const float* __restrict__ b_dpv)
{
    __shared__ float sQ[64][33], sK[64][33], sV[64][33];
    __shared__ float sP[64][16];
    __shared__ float sKdp[16][32], sVdp[16][32];
    __shared__ float sEQ[64][33];
    __shared__ float sEK[16][32];
    __shared__ float sH[32][33];

    const int u    = blockIdx.x;
    const int head = u & 7;
    const int bn   = u >> 3;
    const int tid  = threadIdx.x;

    const float* base = g_qkv + (size_t)bn * (64 * N_QKV) + head * 32;
    for (int i = tid; i < 2048; i += 128) {
        int e = i >> 5, d = i & 31;
        const float* p = base + e * N_QKV + d;
        sQ[e][d] = p[0];
        sK[e][d] = p[256];
        sV[e][d] = p[512];
    }
    __syncthreads();

    if (tid < 64) {
        float l[16];
#pragma unroll
        for (int c = 0; c < 16; c++) l[c] = __ldg(&b_dpk[c]);
#pragma unroll 8
        for (int d = 0; d < 32; d++) {
            float kv = sK[tid][d];
#pragma unroll
            for (int c = 0; c < 16; c++) l[c] += kv * __ldg(&w_dpk[d * 16 + c]);
        }
        float m = l[0];
#pragma unroll
        for (int c = 1; c < 16; c++) m = fmaxf(m, l[c]);
        float s = 0.f;
#pragma unroll
        for (int c = 0; c < 16; c++) { l[c] = expf(l[c] - m); s += l[c]; }
        float inv = 1.f / s;
#pragma unroll
        for (int c = 0; c < 16; c++) sP[tid][c] = l[c] * inv;
    }
    __syncthreads();

#pragma unroll
    for (int r = 0; r < 4; r++) {
        int i = tid + (r << 7);
        int c = i >> 5, d = i & 31;
        float acc = 0.f;
#pragma unroll 8
        for (int e = 0; e < 64; e++) acc += sP[e][c] * sK[e][d];
        sKdp[c][d] = acc;
    }
#pragma unroll
    for (int r = 0; r < 16; r++) {
        int i = tid + (r << 7);
        int g = i >> 5, d = i & 31;
        float acc = 0.f;
        for (int a = 0; a <= g; a++) acc += __ldg(&E[g * 64 + a]) * sQ[a][d];
        sEQ[g][d] = acc;
    }
    __syncthreads();

    if (tid < 64) {
        float l[16];
#pragma unroll
        for (int c = 0; c < 16; c++) l[c] = __ldg(&b_dpv[c]);
#pragma unroll 8
        for (int d = 0; d < 32; d++) {
            float vv = sV[tid][d];
#pragma unroll
            for (int c = 0; c < 16; c++) l[c] += vv * __ldg(&w_dpv[d * 16 + c]);
        }
        float m = l[0];
#pragma unroll
        for (int c = 1; c < 16; c++) m = fmaxf(m, l[c]);
        float s = 0.f;
#pragma unroll
        for (int c = 0; c < 16; c++) { l[c] = expf(l[c] - m); s += l[c]; }
        float inv = 1.f / s;
#pragma unroll
        for (int c = 0; c < 16; c++) sP[tid][c] = l[c] * inv;
    }
    __syncthreads();

#pragma unroll
    for (int r = 0; r < 4; r++) {
        int i = tid + (r << 7);
        int c = i >> 5, d = i & 31;
        float acc = 0.f;
#pragma unroll 8
        for (int e = 0; e < 64; e++) acc += sP[e][c] * sV[e][d];
        sVdp[c][d] = acc;
    }
#pragma unroll
    for (int r = 0; r < 4; r++) {
        int i = tid + (r << 7);
        int g = i >> 5, d = i & 31;
        float acc = 0.f;
        for (int a = 0; a <= g; a++) acc += __ldg(&E[g * 64 + a]) * sKdp[a][d];
        sEK[g][d] = acc;
    }
    __syncthreads();

    if (tid < 64) {
        const int e = tid;
        float st[16];
#pragma unroll
        for (int c = 0; c < 16; c++) {
            float acc = 0.f;
#pragma unroll
            for (int d = 0; d < 32; d++) acc += sEQ[e][d] * sEK[c][d];
            st[c] = acc * 5.656854249492381f;
        }
        float m = st[0];
#pragma unroll
        for (int c = 1; c < 16; c++) m = fmaxf(m, st[c]);
        float s = 0.f;
#pragma unroll
        for (int c = 0; c < 16; c++) { st[c] = expf(st[c] - m); s += st[c]; }
        float inv = 1.f / s;
#pragma unroll
        for (int c = 0; c < 16; c++) st[c] *= inv;
#pragma unroll
        for (int d = 0; d < 32; d++) {
            float acc = 0.f;
#pragma unroll
            for (int c = 0; c < 16; c++) acc += st[c] * sVdp[c][d];
            sEQ[e][d] = acc;
        }
    } else {
        const int idx = tid - 64;
        const int e = idx >> 1, h = idx & 1;
        float sh[16];
#pragma unroll
        for (int j = 0; j < 16; j++) {
            const int f = (h << 4) + j;
            float acc = 0.f;
#pragma unroll 8
            for (int a = 0; a < 64; a++) acc += sQ[a][e] * sK[a][f];
            sh[j] = acc * 8.0f;
        }
        float m = sh[0];
#pragma unroll
        for (int j = 1; j < 16; j++) m = fmaxf(m, sh[j]);
        m = fmaxf(m, __shfl_xor_sync(0xffffffffu, m, 1));
        float s = 0.f;
#pragma unroll
        for (int j = 0; j < 16; j++) { sh[j] = expf(sh[j] - m); s += sh[j]; }
        s += __shfl_xor_sync(0xffffffffu, s, 1);
        float inv = 1.f / s;
#pragma unroll
        for (int j = 0; j < 16; j++) sH[e][(h << 4) + j] = sh[j] * inv;
    }
    __syncthreads();

    uint32_t* otp = g_ot_hl + (size_t)u * 2048;
    uint32_t* ohp = g_oh_hl + (size_t)u * 2048;
#pragma unroll
    for (int r = 0; r < 16; r++) {
        int i = tid + (r << 7);
        int a = i >> 5, e = i & 31;
        otp[i] = packhl(sEQ[a][e]);
        float acc = 0.f;
#pragma unroll
        for (int f = 0; f < 32; f++) acc += sH[e][f] * sV[a][f];
        ohp[i] = packhl(acc);
    }
}

// ======================= BN statistics (deterministic two-stage) =======================
__global__ void __launch_bounds__(256) k_bn_partial(int slot)
{
    const int c = threadIdx.x;
    const size_t base = (size_t)blockIdx.x * 65536;
    float s = 0.f, q = 0.f;
    if (slot == 2) {
        for (int r = 0; r < 256; r++) {
            float v = g_pre[base + (size_t)(r << 8) + c];
            s += v; q += v * v;
        }
    } else {
        const uint32_t* x = slot ? g_oh_hl : g_ot_hl;
        for (int r = 0; r < 256; r++) {
            float v = unpackf(x[base + (size_t)(r << 8) + c]);
            s += v; q += v * v;
        }
    }
    g_psum[slot * 65536 + (blockIdx.x << 8) + c] = s;
    g_psq [slot * 65536 + (blockIdx.x << 8) + c] = q;
}

__global__ void __launch_bounds__(256) k_bn_finalize(
    int slot, const float* __restrict__ g, const float* __restrict__ b)
{
    const int c = threadIdx.x;
    const float* ps = g_psum + slot * 65536;
    const float* pq = g_psq  + slot * 65536;
    float s = 0.f, q = 0.f;
    for (int i = 0; i < 256; i++) { s += ps[(i << 8) + c]; q += pq[(i << 8) + c]; }
    const float inv = 1.f / 65536.f;
    float mean = s * inv;
    float var  = q * inv - mean * mean;
    float rstd = rsqrtf(var + 1e-5f);
    float sc = g[c] * rstd;
    g_S[slot * 256 + c] = sc;
    g_T[slot * 256 + c] = b[c] - mean * sc;
}

// ======================= Final BN apply =======================
__global__ void __launch_bounds__(256) k_bn_apply(float* __restrict__ out)
{
    const size_t i = (size_t)blockIdx.x * 256 + threadIdx.x;
    float4 v = ((const float4*)g_pre)[i];
    const int c = (int)((i & 63) << 2);
    const float* S = g_S + 512;
    const float* T = g_T + 512;
    v.x = v.x * S[c + 0] + T[c + 0];
    v.y = v.y * S[c + 1] + T[c + 1];
    v.z = v.z * S[c + 2] + T[c + 2];
    v.w = v.w * S[c + 3] + T[c + 3];
    ((float4*)out)[i] = v;
}

// ======================= launch =======================
extern "C" void kernel_launch(void* const* d_in, const int* in_sizes, int n_in,
                              void* d_out, int out_size)
{
    const float* src    = (const float*)d_in[0];
    const float* ema    = (const float*)d_in[1];
    const float* w_qkv  = (const float*)d_in[2];
    const float* b_qkv  = (const float*)d_in[3];
    const float* w_dpk  = (const float*)d_in[4];
    const float* b_dpk  = (const float*)d_in[5];
    const float* w_dpv  = (const float*)d_in[6];
    const float* b_dpv  = (const float*)d_in[7];
    const float* bn1_g  = (const float*)d_in[8];
    const float* bn1_b  = (const float*)d_in[9];
    const float* bn2_g  = (const float*)d_in[10];
    const float* bn2_b  = (const float*)d_in[11];
    const float* bna_g  = (const float*)d_in[12];
    const float* bna_b  = (const float*)d_in[13];
    const float* ff1_w1 = (const float*)d_in[14];
    const float* ff1_b1 = (const float*)d_in[15];
    const float* ff1_w2 = (const float*)d_in[16];
    const float* ff1_b2 = (const float*)d_in[17];
    const float* ff2_w1 = (const float*)d_in[18];
    const float* ff2_b1 = (const float*)d_in[19];
    const float* ff2_w2 = (const float*)d_in[20];
    const float* ff2_b2 = (const float*)d_in[21];
    float* out = (float*)d_out;

    // pre-split operands that don't depend on BN stats
    k_split_src<<<16384, 256>>>(src);
    k_prep_w<<<dim3(24,  8), dim3(32, 8)>>>(w_qkv,  WQ_O,  256, 768, -1);
    k_prep_w<<<dim3( 8, 16), dim3(32, 8)>>>(ff1_w2, W2A_O, 512, 256, -1);
    k_prep_w<<<dim3( 8, 16), dim3(32, 8)>>>(ff2_w2, W2B_O, 512, 256, -1);

    k_qkv_tc<<<dim3(N_QKV / 128, M_TOK / 128), 256>>>(b_qkv);
    k_attn<<<NUNITS, 128>>>(ema, w_dpk, b_dpk, w_dpv, b_dpv);
    k_bn_partial<<<256, 256>>>(0);
    k_bn_partial<<<256, 256>>>(1);
    k_bn_finalize<<<1, 256>>>(0, bn1_g, bn1_b);
    k_bn_finalize<<<1, 256>>>(1, bn2_g, bn2_b);

    // BN-folded ff1 weights + bias (need g_S/g_T from finalize)
    k_prep_w<<<dim3(16,  8), dim3(32, 8)>>>(ff1_w1, W1A_O, 256, 512, 0);
    k_prep_w<<<dim3(16,  8), dim3(32, 8)>>>(ff2_w1, W1B_O, 256, 512, 256);
    k_bias1<<<2, 512>>>(ff1_w1, ff1_b1, ff2_w1, ff2_b1);

    k_ff1_tc<<<dim3(D_FF / 128, M_TOK / 128, 2), 256>>>();
    k_g2_tc<<<dim3(C_DIM / 128, M_TOK / 128), 256>>>(ff1_b2, ff2_b2, src);
    k_bn_partial<<<256, 256>>>(2);
    k_bn_finalize<<<1, 256>>>(2, bna_g, bna_b);
    k_bn_apply<<<(M_TOK * C_DIM / 4) / 256, 256>>>(out);
}